// round 14
// baseline (speedup 1.0000x reference)
#include <cuda_runtime.h>
#include <cuda_fp16.h>
#include <cstdint>
#include <math.h>

#define B_ 16
#define R_ 1024
#define F_ 128
#define D_ 128
#define K_ 7
#define H_ 512
#define H2_ 256
#define FEAT_ 263   // 2*D + K
#define NB1_ 32     // k1 blocks per batch (32 rows each)
#define NB3_ 32     // k3 blocks per batch (32 rows each)
#define K1_SMEM (8 * 2 * 896 * 4)   // 57344 B: per-warp double row buffers

// ---------------- device scratch (static, allocation-free) ----------------
__device__ __half E_h[B_ * R_ * F_];         // exp(masked S), fp16
__device__ float Zrow_g[B_ * R_];
__device__ float pscore_g[B_ * R_];
__device__ float Zcolp_g[B_ * NB1_ * F_];
__device__ float ligcolp_g[B_ * NB1_ * F_];
__device__ float abarp_g[B_ * NB1_ * F_];
__device__ float tstrp_g[B_ * NB1_ * 8];
__device__ float Pwp_g[B_ * NB3_ * D_];
__device__ float Cwp_g[B_ * NB3_ * D_];
// per-batch finalized quantities (written by elected blocks)
__device__ float lcoef_g[B_ * F_];
__device__ float lw_g[B_ * F_];
__device__ float la_g[B_ * F_];
__device__ float scal_g[B_ * 4];             // ip, il, spw, slw
__device__ float tst_g[B_ * 8];
__device__ float Pws_g[B_ * D_];
__device__ float Cws_g[B_ * D_];
__device__ unsigned int cnt1_g[B_];          // self-resetting election counters
__device__ unsigned int cnt3_g[B_];

// ---------------- helpers ----------------
__device__ __forceinline__ float warpSum(float v) {
    #pragma unroll
    for (int o = 16; o > 0; o >>= 1) v += __shfl_down_sync(0xffffffffu, v, o);
    return v;
}
__device__ __forceinline__ float warpAllSum(float v) {
    #pragma unroll
    for (int o = 16; o > 0; o >>= 1) v += __shfl_xor_sync(0xffffffffu, v, o);
    return v;
}
__device__ __forceinline__ float blockReduceSum(float v, float* sm) {
    int lane = threadIdx.x & 31, w = threadIdx.x >> 5;
    int nw = (blockDim.x + 31) >> 5;
    v = warpSum(v);
    if (lane == 0) sm[w] = v;
    __syncthreads();
    float r = (threadIdx.x < nw) ? sm[threadIdx.x] : 0.0f;
    if (w == 0) r = warpSum(r);
    if (threadIdx.x == 0) sm[0] = r;
    __syncthreads();
    r = sm[0];
    __syncthreads();
    return r;
}
__device__ __forceinline__ void l2pf(const void* p) {
    asm volatile("prefetch.global.L2 [%0];" :: "l"(p));
}
__device__ __forceinline__ void cpasync16(unsigned int saddr, const void* gptr) {
    asm volatile("cp.async.cg.shared.global [%0], [%1], 16;" :: "r"(saddr), "l"(gptr));
}
__device__ __forceinline__ void cpasync_commit() {
    asm volatile("cp.async.commit_group;" ::: "memory");
}
template<int N>
__device__ __forceinline__ void cpasync_wait() {
    asm volatile("cp.async.wait_group %0;" :: "n"(N) : "memory");
}

// per-element softmax+weights macro
#define ELEM(X0,X1,X2,X3,X4,X5,X6, PMF, MEXF, EOUT, ZC, LC) do {              \
    float e0_=__expf(X0), e1_=__expf(X1), e2_=__expf(X2), e3_=__expf(X3);      \
    float e4_=__expf(X4), e5_=__expf(X5), e6_=__expf(X6);                      \
    float s_ = ((e0_+e1_)+(e2_+e3_))+((e4_+e5_)+e6_);                          \
    float inv_ = __fdividef(1.0f, s_);                                         \
    float h_ = e0_*wshr[0]; h_=fmaf(e1_,wshr[1],h_); h_=fmaf(e2_,wshr[2],h_);  \
    h_=fmaf(e3_,wshr[3],h_); h_=fmaf(e4_,wshr[4],h_);                          \
    h_=fmaf(e5_,wshr[5],h_); h_=fmaf(e6_,wshr[6],h_);                          \
    tk[0]=fmaf(e0_,inv_,tk[0]); tk[1]=fmaf(e1_,inv_,tk[1]);                    \
    tk[2]=fmaf(e2_,inv_,tk[2]); tk[3]=fmaf(e3_,inv_,tk[3]);                    \
    tk[4]=fmaf(e4_,inv_,tk[4]); tk[5]=fmaf(e5_,inv_,tk[5]);                    \
    tk[6]=fmaf(e6_,inv_,tk[6]);                                                \
    float Sm_ = h_*inv_*(PMF);                                                 \
    float E_ = __expf(Sm_);                                                    \
    EOUT = E_; rowS += Sm_; rowE = fmaf(E_, (MEXF), rowE);                     \
    ZC = fmaf(E_, mexr, ZC); LC += Sm_;                                        \
} while(0)

// ====== K1: main pass + per-batch finalize via last-block election =========
__global__ void __launch_bounds__(256, 4) k1_logits(const float* __restrict__ logits,
                          const float* __restrict__ fg_mask,
                          const float* __restrict__ prot_mask,
                          const float* __restrict__ tw) {
    extern __shared__ __align__(16) float dbuf[];   // 8 warps x 2 x 896 floats
    int b = blockIdx.y, blk = blockIdx.x;
    int tid = threadIdx.x, w = tid >> 5, t = tid & 31;

    __shared__ float tks[8][8];
    __shared__ float wsh_s[8];
    __shared__ unsigned int lastsh;

    if (tid < K_) {
        float x = tw[tid];
        wsh_s[tid] = fmaxf(x, 0.0f) + log1pf(expf(-fabsf(x)));
    }
    __syncthreads();
    float wshr[K_];
    #pragma unroll
    for (int k = 0; k < K_; k++) wshr[k] = wsh_s[k];

    float4 fg4 = ((const float4*)(fg_mask + b * F_))[t];
    float mexf0 = __expf(-(1.0f - fg4.x) * 1e9f);
    float mexf1 = __expf(-(1.0f - fg4.y) * 1e9f);
    float mexf2 = __expf(-(1.0f - fg4.z) * 1e9f);
    float mexf3 = __expf(-(1.0f - fg4.w) * 1e9f);

    float zc0=0.f,zc1=0.f,zc2=0.f,zc3=0.f;
    float lc0=0.f,lc1=0.f,lc2=0.f,lc3=0.f;
    float ab0=0.f,ab1=0.f,ab2=0.f,ab3=0.f;
    float tk[K_];
    #pragma unroll
    for (int k = 0; k < K_; k++) tk[k] = 0.0f;

    int r0 = blk * 32 + w * 4;
    float* wbuf = dbuf + w * 1792;
    unsigned int sb = (unsigned int)__cvta_generic_to_shared(wbuf);

    const float* lbase = logits + (size_t)(b * R_) * 896;
    {   // prologue: row 0 -> buffer 0
        const float4* src = (const float4*)(lbase + (size_t)r0 * 896);
        #pragma unroll
        for (int j = 0; j < 7; j++) cpasync16(sb + (t + 32 * j) * 16, src + t + 32 * j);
        cpasync_commit();
    }

    for (int i = 0; i < 4; i++) {
        if (i < 3) {
            const float4* src = (const float4*)(lbase + (size_t)(r0 + i + 1) * 896);
            unsigned int sa = sb + ((i + 1) & 1) * 3584;
            #pragma unroll
            for (int j = 0; j < 7; j++) cpasync16(sa + (t + 32 * j) * 16, src + t + 32 * j);
            cpasync_commit();
            cpasync_wait<1>();
        } else {
            cpasync_wait<0>();
        }
        __syncwarp();

        int r = r0 + i;
        const float4* bp4 = (const float4*)(wbuf + (i & 1) * 896 + t * 28);
        float pm = prot_mask[b * R_ + r];
        float mexr = __expf(-(1.0f - pm) * 1e9f);
        float rowS = 0.0f, rowE = 0.0f;
        float E0, E1, E2, E3;

        {
            float4 v0 = bp4[0], v1 = bp4[1], v2 = bp4[2], v3 = bp4[3];
            ELEM(v0.x, v0.y, v0.z, v0.w, v1.x, v1.y, v1.z, pm * fg4.x, mexf0, E0, zc0, lc0);
            ELEM(v1.w, v2.x, v2.y, v2.z, v2.w, v3.x, v3.y, pm * fg4.y, mexf1, E1, zc1, lc1);
            float4 v4 = bp4[4], v5 = bp4[5], v6 = bp4[6];
            ELEM(v3.z, v3.w, v4.x, v4.y, v4.z, v4.w, v5.x, pm * fg4.z, mexf2, E2, zc2, lc2);
            ELEM(v5.y, v5.z, v5.w, v6.x, v6.y, v6.z, v6.w, pm * fg4.w, mexf3, E3, zc3, lc3);
        }

        {   // packed fp16 store: one STG.64
            __half2 ha = __halves2half2(__float2half_rn(E0), __float2half_rn(E1));
            __half2 hb = __halves2half2(__float2half_rn(E2), __float2half_rn(E3));
            uint2 pk;
            pk.x = *reinterpret_cast<unsigned int*>(&ha);
            pk.y = *reinterpret_cast<unsigned int*>(&hb);
            ((uint2*)(E_h + (size_t)(b * R_ + r) * F_))[t] = pk;
        }

        rowS = warpAllSum(rowS);
        rowE = warpAllSum(rowE);
        float ps = rowS * pm;
        if (t == 0) { pscore_g[b * R_ + r] = ps; Zrow_g[b * R_ + r] = rowE; }
        float coef = __fdividef(ps, rowE);
        ab0 = fmaf(coef, E0, ab0);
        ab1 = fmaf(coef, E1, ab1);
        ab2 = fmaf(coef, E2, ab2);
        ab3 = fmaf(coef, E3, ab3);
        __syncwarp();
    }

    // epilogue: block-wide reduction into deterministic partial slots
    #pragma unroll
    for (int k = 0; k < K_; k++) { float v = warpSum(tk[k]); if (t == 0) tks[w][k] = v; }
    __syncthreads();
    float4* bb4 = (float4*)dbuf;
    bb4[w * 32 + t]       = make_float4(zc0, zc1, zc2, zc3);
    bb4[256 + w * 32 + t] = make_float4(lc0, lc1, lc2, lc3);
    bb4[512 + w * 32 + t] = make_float4(ab0, ab1, ab2, ab3);
    __syncthreads();
    if (tid < 128) {
        float s = 0.0f, s2 = 0.0f, s3 = 0.0f;
        #pragma unroll
        for (int ww = 0; ww < 8; ww++) {
            s  += dbuf[ww * 128 + tid];
            s2 += dbuf[1024 + ww * 128 + tid];
            s3 += dbuf[2048 + ww * 128 + tid];
        }
        Zcolp_g[(size_t)(b * NB1_ + blk) * F_ + tid]   = s;
        ligcolp_g[(size_t)(b * NB1_ + blk) * F_ + tid] = s2;
        abarp_g[(size_t)(b * NB1_ + blk) * F_ + tid]   = s3;
    } else if (tid < 128 + K_) {
        int k = tid - 128;
        float s = 0.0f;
        #pragma unroll
        for (int ww = 0; ww < 8; ww++) s += tks[ww][k];
        tstrp_g[(size_t)(b * NB1_ + blk) * 8 + k] = s * wshr[k];
    }

    // ---- per-batch finalize: last block computes lcoef/lw/la/scal/tst ----
    __threadfence();
    __syncthreads();
    if (tid == 0) lastsh = atomicInc(&cnt1_g[b], NB1_ - 1);
    __syncthreads();
    if (lastsh != NB1_ - 1) {
#if __CUDA_ARCH__ >= 900
        cudaTriggerProgrammaticLaunchCompletion();
#endif
        return;
    }
    __threadfence();

    {
        int f = tid & 127, q = tid >> 7;
        float vv = pscore_g[b*R_+tid] + pscore_g[b*R_+256+tid]
                 + pscore_g[b*R_+512+tid] + pscore_g[b*R_+768+tid];
        float psum = blockReduceSum(vv, (float*)tks);
        float ip = __fdividef(1.0f, psum + 1e-8f);

        float zs2 = 0.0f, ls2 = 0.0f, as2 = 0.0f;
        for (int s = q * 16; s < q * 16 + 16; s++) {
            zs2 += Zcolp_g[(size_t)(b * NB1_ + s) * F_ + f];
            ls2 += ligcolp_g[(size_t)(b * NB1_ + s) * F_ + f];
            as2 += abarp_g[(size_t)(b * NB1_ + s) * F_ + f];
        }
        dbuf[q * 128 + f]       = zs2;
        dbuf[256 + q * 128 + f] = ls2;
        dbuf[512 + q * 128 + f] = as2;
        __syncthreads();
        float lw0 = 0.0f, Zc = 1.0f, absum = 0.0f, fgv = 0.0f;
        if (tid < 128) {
            Zc    = dbuf[tid] + dbuf[128 + tid];
            float lgc = dbuf[256 + tid] + dbuf[384 + tid];
            absum = dbuf[512 + tid] + dbuf[640 + tid];
            fgv = fg_mask[b * F_ + tid];
            lw0 = lgc * fgv;
        }
        float lsum = blockReduceSum(lw0, (float*)tks);
        float il = __fdividef(1.0f, lsum + 1e-8f);
        if (tid < 128) {
            lcoef_g[b * F_ + tid] = __fdividef(lw0, Zc);
            lw_g[b * F_ + tid] = lw0 * il;
            float mexf = __expf(-(1.0f - fgv) * 1e9f);
            la_g[b * F_ + tid] = absum * mexf * ip;
        }
        if (tid == 0) {
            scal_g[b*4+0] = ip; scal_g[b*4+1] = il;
            scal_g[b*4+2] = psum * ip; scal_g[b*4+3] = lsum * il;
        }
        if (tid < K_) {
            float s = 0.0f;
            #pragma unroll
            for (int s2 = 0; s2 < NB1_; s2++) s += tstrp_g[(size_t)(b * NB1_ + s2) * 8 + tid];
            tst_g[b * 8 + tid] = s;
        }
    }
#if __CUDA_ARCH__ >= 900
    cudaTriggerProgrammaticLaunchCompletion();
#endif
}

// ====== K3: lean E pass (no prolog) + Pw/Cw finalize via election ==========
__global__ void __launch_bounds__(256, 6) k3_epass(const float* __restrict__ protein_emb,
                        const float* __restrict__ ligand_emb,
                        const float* __restrict__ fg_mask,
                        const float* __restrict__ prot_mask,
                        const float* __restrict__ Wr, const float* __restrict__ Wf,
                        const float* __restrict__ W1, const float* __restrict__ W2) {
    int b = blockIdx.y, blk = blockIdx.x;
    int tid = threadIdx.x, w = tid >> 5, t = tid & 31;
    int f = tid & 127, q = tid >> 7;

    __shared__ __align__(16) float stage[2048];
    __shared__ unsigned int lastsh;

    // PDL prolog: L2 prefetch of head weights + ligand
    {
        int gb = b * NB3_ + blk;                       // 0..511
        long gid = (long)gb * 256 + tid;
        const long n1 = 4208, n2 = 4096, nr = 512, nl = 8192;
        if (gid < n1)                      l2pf((const char*)W1 + gid * 128);
        else if (gid < n1+n2)              l2pf((const char*)W2 + (gid-n1) * 128);
        else if (gid < n1+n2+nr)           l2pf((const char*)Wr + (gid-n1-n2) * 128);
        else if (gid < n1+n2+2*nr)         l2pf((const char*)Wf + (gid-n1-n2-nr) * 128);
        else if (gid < n1+n2+2*nr+nl)      l2pf((const char*)ligand_emb + (gid-n1-n2-2*nr) * 128);
    }
#if __CUDA_ARCH__ >= 900
    cudaGridDependencySynchronize();
#endif

    float4 lco4 = ((const float4*)(lcoef_g + b * F_))[t];

    // row loop: 8 warps x 4 rows, lane t owns f=4t..4t+3
    float4 Pa = make_float4(0.f, 0.f, 0.f, 0.f);
    float4 Ca = make_float4(0.f, 0.f, 0.f, 0.f);
    int rbase = blk * 32 + w * 4;
    #pragma unroll
    for (int i = 0; i < 4; i++) {
        int r = rbase + i;
        float ps = pscore_g[b * R_ + r];
        float pm = prot_mask[b * R_ + r];
        float mexr = __expf(-(1.0f - pm) * 1e9f);
        uint2 e2v = ((const uint2*)(E_h + (size_t)(b * R_ + r) * F_))[t];
        __half2 ha = *reinterpret_cast<__half2*>(&e2v.x);
        __half2 hb = *reinterpret_cast<__half2*>(&e2v.y);
        float2 fa = __half22float2(ha);
        float2 fb = __half22float2(hb);
        float dv = lco4.x * fa.x + lco4.y * fa.y + lco4.z * fb.x + lco4.w * fb.y;
        float craw = mexr * warpAllSum(dv);
        float4 P4 = ((const float4*)(protein_emb + (size_t)(b * R_ + r) * D_))[t];
        Pa.x = fmaf(ps, P4.x, Pa.x); Pa.y = fmaf(ps, P4.y, Pa.y);
        Pa.z = fmaf(ps, P4.z, Pa.z); Pa.w = fmaf(ps, P4.w, Pa.w);
        Ca.x = fmaf(craw, P4.x, Ca.x); Ca.y = fmaf(craw, P4.y, Ca.y);
        Ca.z = fmaf(craw, P4.z, Ca.z); Ca.w = fmaf(craw, P4.w, Ca.w);
    }

    __syncthreads();
    float4* st4 = (float4*)stage;
    st4[w * 32 + t]       = Pa;
    st4[256 + w * 32 + t] = Ca;
    __syncthreads();
    if (tid < 128) {
        float s = 0.0f;
        #pragma unroll
        for (int ww = 0; ww < 8; ww++) s += stage[ww * 128 + tid];
        Pwp_g[(size_t)(b * NB3_ + blk) * D_ + tid] = s;
    } else {
        float s = 0.0f;
        #pragma unroll
        for (int ww = 0; ww < 8; ww++) s += stage[1024 + ww * 128 + f];
        Cwp_g[(size_t)(b * NB3_ + blk) * D_ + f] = s;
    }

    // ---- per-batch finalize: last block collapses Pwp/Cwp, prescaled ----
    __threadfence();
    __syncthreads();
    if (tid == 0) lastsh = atomicInc(&cnt3_g[b], NB3_ - 1);
    __syncthreads();
    if (lastsh != NB3_ - 1) {
#if __CUDA_ARCH__ >= 900
        cudaTriggerProgrammaticLaunchCompletion();
#endif
        return;
    }
    __threadfence();
    {
        float ip = scal_g[b*4+0], il = scal_g[b*4+1];
        float aP = 0.0f, aC = 0.0f;
        for (int s = q * 16; s < q * 16 + 16; s++) {
            aP += Pwp_g[(size_t)(b * NB3_ + s) * D_ + f];
            aC += Cwp_g[(size_t)(b * NB3_ + s) * D_ + f];
        }
        stage[q * 128 + f]       = aP;
        stage[512 + q * 128 + f] = aC;
        __syncthreads();
        if (tid < 128) {
            Pws_g[b * D_ + tid] = (stage[tid] + stage[128 + tid]) * ip;
            Cws_g[b * D_ + tid] = (stage[512 + tid] + stage[640 + tid]) * il;
        }
    }
#if __CUDA_ARCH__ >= 900
    cudaTriggerProgrammaticLaunchCompletion();
#endif
}

// ====== KHEAD: pure tail — pooling + feat + norm + MLP =====================
__global__ void __launch_bounds__(1024, 1) khead(const float* __restrict__ ligand_emb,
                        const float* __restrict__ fg_mask,
                        const float* __restrict__ Wr, const float* __restrict__ br,
                        const float* __restrict__ Wf, const float* __restrict__ bf,
                        const float* __restrict__ W1, const float* __restrict__ b1,
                        const float* __restrict__ W2, const float* __restrict__ b2,
                        const float* __restrict__ W3, const float* __restrict__ b3,
                        float* __restrict__ dout, int osz) {
    int b = blockIdx.x, tid = threadIdx.x, w = tid >> 5, t = tid & 31;
    int f = tid & 127, q = tid >> 7;

    __shared__ float red[32];
    __shared__ float big[2048];
    __shared__ float lw_sm[128], la_s[128];
    __shared__ float Pws[128], Cws[128];
    __shared__ float gs[128], Ls[128];
    __shared__ float feat[FEAT_ + 1];
    __shared__ float h1[H_], h2[H2_];
    __shared__ float tst[8];

    // PDL prolog
    if (b == 0) for (int i = B_ + B_ * FEAT_ + tid; i < osz; i += 1024) dout[i] = 0.0f;
#if __CUDA_ARCH__ >= 900
    cudaGridDependencySynchronize();
#endif

    float spw = scal_g[b*4+2], slw = scal_g[b*4+3];
    if (tid < 128) {
        la_s[tid]  = la_g[b * F_ + tid];
        lw_sm[tid] = lw_g[b * F_ + tid];
        Pws[tid]   = Pws_g[b * D_ + tid];
        Cws[tid]   = Cws_g[b * D_ + tid];
    }
    if (tid < K_) tst[tid] = tst_g[b * 8 + tid];
    __syncthreads();

    // ligand pooling: 8 f-chunks x 128 d
    {
        float ag = 0.0f, aL = 0.0f;
        #pragma unroll
        for (int i = 0; i < 16; i++) {
            int ff = q * 16 + i;
            float lv = ligand_emb[(size_t)(b * F_ + ff) * D_ + f];
            ag += la_s[ff] * lv;
            aL += lw_sm[ff] * lv;
        }
        big[q * 128 + f] = ag;
        big[1024 + q * 128 + f] = aL;
    }
    __syncthreads();
    if (tid < 128) {
        float g = 0.0f, L = 0.0f;
        #pragma unroll
        for (int j = 0; j < 8; j++) { g += big[j * 128 + tid]; L += big[1024 + j * 128 + tid]; }
        gs[tid] = g; Ls[tid] = L;
    }
    __syncthreads();

    // feat rows: warps 0-15 -> Wr/gs, 16-31 -> Wf/Cws
    {
        const float* Wm = (w < 16) ? Wr : Wf;
        const float* vec = (w < 16) ? gs : Cws;
        int rb = (w & 15) * 8;
        #pragma unroll 1
        for (int i = 0; i < 2; i++) {
            int r0 = rb + i * 4;
            float p0=0.f,p1=0.f,p2=0.f,p3=0.f;
            #pragma unroll
            for (int u = 0; u < 4; u++) {
                int j = t + 32 * u;
                float g = vec[j];
                p0 += Wm[(r0+0)*D_ + j] * g;
                p1 += Wm[(r0+1)*D_ + j] * g;
                p2 += Wm[(r0+2)*D_ + j] * g;
                p3 += Wm[(r0+3)*D_ + j] * g;
            }
            p0 = warpSum(p0); p1 = warpSum(p1); p2 = warpSum(p2); p3 = warpSum(p3);
            if (t == 0) {
                if (w < 16) {
                    feat[r0+0] = Pws[r0+0] + p0 + spw * br[r0+0];
                    feat[r0+1] = Pws[r0+1] + p1 + spw * br[r0+1];
                    feat[r0+2] = Pws[r0+2] + p2 + spw * br[r0+2];
                    feat[r0+3] = Pws[r0+3] + p3 + spw * br[r0+3];
                } else {
                    feat[128+r0+0] = Ls[r0+0] + p0 + slw * bf[r0+0];
                    feat[128+r0+1] = Ls[r0+1] + p1 + slw * bf[r0+1];
                    feat[128+r0+2] = Ls[r0+2] + p2 + slw * bf[r0+2];
                    feat[128+r0+3] = Ls[r0+3] + p3 + slw * bf[r0+3];
                }
            }
        }
    }
    if (tid < K_) feat[2 * D_ + tid] = tst[tid];
    __syncthreads();

    // norm + normalized-feat output
    float sv = (tid < FEAT_) ? feat[tid] * feat[tid] : 0.0f;
    float nrm = blockReduceSum(sv, red);
    float inv = 1.0f / fmaxf(sqrtf(nrm), 1e-12f);
    if (tid < FEAT_) {
        int oi = B_ + b * FEAT_ + tid;
        if (oi < osz) dout[oi] = feat[tid] * inv;
    }

    // MLP layer 1: 512 rows, 16/warp, 4 per iteration
    {
        int rb = w * 16;
        #pragma unroll 1
        for (int i = 0; i < 4; i++) {
            int r0 = rb + i * 4;
            float p0=0.f,p1=0.f,p2=0.f,p3=0.f;
            #pragma unroll
            for (int u = 0; u < 8; u++) {
                int j = t + 32 * u;
                float fv = feat[j];
                p0 += W1[(r0+0)*FEAT_ + j] * fv;
                p1 += W1[(r0+1)*FEAT_ + j] * fv;
                p2 += W1[(r0+2)*FEAT_ + j] * fv;
                p3 += W1[(r0+3)*FEAT_ + j] * fv;
            }
            if (t < 7) {
                int j = 256 + t;
                float fv = feat[j];
                p0 += W1[(r0+0)*FEAT_ + j] * fv;
                p1 += W1[(r0+1)*FEAT_ + j] * fv;
                p2 += W1[(r0+2)*FEAT_ + j] * fv;
                p3 += W1[(r0+3)*FEAT_ + j] * fv;
            }
            p0 = warpSum(p0); p1 = warpSum(p1); p2 = warpSum(p2); p3 = warpSum(p3);
            if (t == 0) {
                h1[r0+0] = fmaxf(p0 + b1[r0+0], 0.0f);
                h1[r0+1] = fmaxf(p1 + b1[r0+1], 0.0f);
                h1[r0+2] = fmaxf(p2 + b1[r0+2], 0.0f);
                h1[r0+3] = fmaxf(p3 + b1[r0+3], 0.0f);
            }
        }
    }
    __syncthreads();

    // MLP layer 2: 256 rows, 8/warp, 2 per iteration
    {
        int rb = w * 8;
        #pragma unroll 1
        for (int i = 0; i < 4; i++) {
            int r0 = rb + i * 2;
            float p0=0.f,p1=0.f;
            #pragma unroll
            for (int u = 0; u < 16; u++) {
                int j = t + 32 * u;
                float hv = h1[j];
                p0 += W2[(r0+0)*H_ + j] * hv;
                p1 += W2[(r0+1)*H_ + j] * hv;
            }
            p0 = warpSum(p0); p1 = warpSum(p1);
            if (t == 0) {
                h2[r0+0] = fmaxf(p0 + b2[r0+0], 0.0f);
                h2[r0+1] = fmaxf(p1 + b2[r0+1], 0.0f);
            }
        }
    }
    __syncthreads();
    float pv = (tid < H2_) ? W3[tid] * h2[tid] : 0.0f;
    float pred = blockReduceSum(pv, red);
    if (tid == 0 && b < osz) dout[b] = pred + b3[0];
}

// ---------------- launch ----------------
extern "C" void kernel_launch(void* const* d_in, const int* in_sizes, int n_in,
                              void* d_out, int out_size) {
    const float* lig    = (const float*)d_in[0];
    const float* prot   = (const float*)d_in[1];
    const float* logits = (const float*)d_in[2];
    const float* fg     = (const float*)d_in[3];
    const float* pmsk   = (const float*)d_in[4];
    const float* tw     = (const float*)d_in[5];
    const float* Wr = (const float*)d_in[6];  const float* br = (const float*)d_in[7];
    const float* Wf = (const float*)d_in[8];  const float* bf = (const float*)d_in[9];
    const float* W1 = (const float*)d_in[10]; const float* b1 = (const float*)d_in[11];
    const float* W2 = (const float*)d_in[12]; const float* b2 = (const float*)d_in[13];
    const float* W3 = (const float*)d_in[14]; const float* b3 = (const float*)d_in[15];
    float* out = (float*)d_out;

    static int smem_set = 0;
    if (!smem_set) {
        cudaFuncSetAttribute(k1_logits, cudaFuncAttributeMaxDynamicSharedMemorySize, K1_SMEM);
        smem_set = 1;
    }

    k1_logits<<<dim3(NB1_, B_), 256, K1_SMEM>>>(logits, fg, pmsk, tw);

    {
        cudaLaunchConfig_t cfg = {};
        cfg.gridDim = dim3(NB3_, B_);
        cfg.blockDim = dim3(256, 1, 1);
        cfg.dynamicSmemBytes = 0;
        cfg.stream = 0;
        cudaLaunchAttribute attrs[1];
        attrs[0].id = cudaLaunchAttributeProgrammaticStreamSerialization;
        attrs[0].val.programmaticStreamSerializationAllowed = 1;
        cfg.attrs = attrs;
        cfg.numAttrs = 1;
        cudaLaunchKernelEx(&cfg, k3_epass, prot, lig, fg, pmsk, Wr, Wf, W1, W2);
    }

    {
        cudaLaunchConfig_t cfg = {};
        cfg.gridDim = dim3(B_, 1, 1);
        cfg.blockDim = dim3(1024, 1, 1);
        cfg.dynamicSmemBytes = 0;
        cfg.stream = 0;
        cudaLaunchAttribute attrs[1];
        attrs[0].id = cudaLaunchAttributeProgrammaticStreamSerialization;
        attrs[0].val.programmaticStreamSerializationAllowed = 1;
        cfg.attrs = attrs;
        cfg.numAttrs = 1;
        cudaLaunchKernelEx(&cfg, khead, lig, fg, Wr, br, Wf, bf,
                           W1, b1, W2, b2, W3, b3, out, out_size);
    }
}

// round 15
// speedup vs baseline: 1.0788x; 1.0788x over previous
#include <cuda_runtime.h>
#include <cuda_fp16.h>
#include <cstdint>
#include <math.h>

#define B_ 16
#define R_ 1024
#define F_ 128
#define D_ 128
#define K_ 7
#define H_ 512
#define H2_ 256
#define FEAT_ 263   // 2*D + K
#define NB1_ 32     // k1 blocks per batch (32 rows each)
#define NB3_ 32     // k3 blocks per batch (32 rows each)
#define K1_SMEM (8 * 2 * 896 * 4)   // 57344 B: per-warp double row buffers

// ---------------- device scratch (static, allocation-free) ----------------
__device__ __half E_h[B_ * R_ * F_];         // exp(masked S), fp16
__device__ float Zrow_g[B_ * R_];
__device__ float pscore_g[B_ * R_];
__device__ float Zcolp_g[B_ * NB1_ * F_];
__device__ float ligcolp_g[B_ * NB1_ * F_];
__device__ float abarp_g[B_ * NB1_ * F_];
__device__ float tstrp_g[B_ * NB1_ * 8];
__device__ float Pwp_g[B_ * NB3_ * D_];
__device__ float Cwp_g[B_ * NB3_ * D_];
// per-batch finalized quantities (written by k3's elected blocks)
__device__ float lw_g[B_ * F_];
__device__ float la_g[B_ * F_];
__device__ float scal_g[B_ * 4];             // ip, il, spw, slw
__device__ float tst_g[B_ * 8];
__device__ float Pws_g[B_ * D_];
__device__ float Cws_g[B_ * D_];
__device__ unsigned int cnt3_g[B_];          // self-resetting election counters

// ---------------- helpers ----------------
__device__ __forceinline__ float warpSum(float v) {
    #pragma unroll
    for (int o = 16; o > 0; o >>= 1) v += __shfl_down_sync(0xffffffffu, v, o);
    return v;
}
__device__ __forceinline__ float warpAllSum(float v) {
    #pragma unroll
    for (int o = 16; o > 0; o >>= 1) v += __shfl_xor_sync(0xffffffffu, v, o);
    return v;
}
__device__ __forceinline__ float blockReduceSum(float v, float* sm) {
    int lane = threadIdx.x & 31, w = threadIdx.x >> 5;
    int nw = (blockDim.x + 31) >> 5;
    v = warpSum(v);
    if (lane == 0) sm[w] = v;
    __syncthreads();
    float r = (threadIdx.x < nw) ? sm[threadIdx.x] : 0.0f;
    if (w == 0) r = warpSum(r);
    if (threadIdx.x == 0) sm[0] = r;
    __syncthreads();
    r = sm[0];
    __syncthreads();
    return r;
}
__device__ __forceinline__ void l2pf(const void* p) {
    asm volatile("prefetch.global.L2 [%0];" :: "l"(p));
}
__device__ __forceinline__ void cpasync16(unsigned int saddr, const void* gptr) {
    asm volatile("cp.async.cg.shared.global [%0], [%1], 16;" :: "r"(saddr), "l"(gptr));
}
__device__ __forceinline__ void cpasync_commit() {
    asm volatile("cp.async.commit_group;" ::: "memory");
}
template<int N>
__device__ __forceinline__ void cpasync_wait() {
    asm volatile("cp.async.wait_group %0;" :: "n"(N) : "memory");
}

// per-element softmax+weights macro
#define ELEM(X0,X1,X2,X3,X4,X5,X6, PMF, MEXF, EOUT, ZC, LC) do {              \
    float e0_=__expf(X0), e1_=__expf(X1), e2_=__expf(X2), e3_=__expf(X3);      \
    float e4_=__expf(X4), e5_=__expf(X5), e6_=__expf(X6);                      \
    float s_ = ((e0_+e1_)+(e2_+e3_))+((e4_+e5_)+e6_);                          \
    float inv_ = __fdividef(1.0f, s_);                                         \
    float h_ = e0_*wshr[0]; h_=fmaf(e1_,wshr[1],h_); h_=fmaf(e2_,wshr[2],h_);  \
    h_=fmaf(e3_,wshr[3],h_); h_=fmaf(e4_,wshr[4],h_);                          \
    h_=fmaf(e5_,wshr[5],h_); h_=fmaf(e6_,wshr[6],h_);                          \
    tk[0]=fmaf(e0_,inv_,tk[0]); tk[1]=fmaf(e1_,inv_,tk[1]);                    \
    tk[2]=fmaf(e2_,inv_,tk[2]); tk[3]=fmaf(e3_,inv_,tk[3]);                    \
    tk[4]=fmaf(e4_,inv_,tk[4]); tk[5]=fmaf(e5_,inv_,tk[5]);                    \
    tk[6]=fmaf(e6_,inv_,tk[6]);                                                \
    float Sm_ = h_*inv_*(PMF);                                                 \
    float E_ = __expf(Sm_);                                                    \
    EOUT = E_; rowS += Sm_; rowE = fmaf(E_, (MEXF), rowE);                     \
    ZC = fmaf(E_, mexr, ZC); LC += Sm_;                                        \
} while(0)

// ====== K1: EXACT R13 — warp-private cp.async double-buffered staging ======
__global__ void __launch_bounds__(256, 4) k1_logits(const float* __restrict__ logits,
                          const float* __restrict__ fg_mask,
                          const float* __restrict__ prot_mask,
                          const float* __restrict__ tw) {
    extern __shared__ __align__(16) float dbuf[];   // 8 warps x 2 x 896 floats
    int b = blockIdx.y, blk = blockIdx.x;
    int tid = threadIdx.x, w = tid >> 5, t = tid & 31;

    __shared__ float tks[8][8];
    __shared__ float wsh_s[8];

    if (tid < K_) {
        float x = tw[tid];
        wsh_s[tid] = fmaxf(x, 0.0f) + log1pf(expf(-fabsf(x)));
    }
    __syncthreads();
    float wshr[K_];
    #pragma unroll
    for (int k = 0; k < K_; k++) wshr[k] = wsh_s[k];

    float4 fg4 = ((const float4*)(fg_mask + b * F_))[t];
    float mexf0 = __expf(-(1.0f - fg4.x) * 1e9f);
    float mexf1 = __expf(-(1.0f - fg4.y) * 1e9f);
    float mexf2 = __expf(-(1.0f - fg4.z) * 1e9f);
    float mexf3 = __expf(-(1.0f - fg4.w) * 1e9f);

    float zc0=0.f,zc1=0.f,zc2=0.f,zc3=0.f;
    float lc0=0.f,lc1=0.f,lc2=0.f,lc3=0.f;
    float ab0=0.f,ab1=0.f,ab2=0.f,ab3=0.f;
    float tk[K_];
    #pragma unroll
    for (int k = 0; k < K_; k++) tk[k] = 0.0f;

    int r0 = blk * 32 + w * 4;
    float* wbuf = dbuf + w * 1792;
    unsigned int sb = (unsigned int)__cvta_generic_to_shared(wbuf);

    const float* lbase = logits + (size_t)(b * R_) * 896;
    {   // prologue: row 0 -> buffer 0
        const float4* src = (const float4*)(lbase + (size_t)r0 * 896);
        #pragma unroll
        for (int j = 0; j < 7; j++) cpasync16(sb + (t + 32 * j) * 16, src + t + 32 * j);
        cpasync_commit();
    }

    for (int i = 0; i < 4; i++) {
        if (i < 3) {
            const float4* src = (const float4*)(lbase + (size_t)(r0 + i + 1) * 896);
            unsigned int sa = sb + ((i + 1) & 1) * 3584;
            #pragma unroll
            for (int j = 0; j < 7; j++) cpasync16(sa + (t + 32 * j) * 16, src + t + 32 * j);
            cpasync_commit();
            cpasync_wait<1>();
        } else {
            cpasync_wait<0>();
        }
        __syncwarp();

        int r = r0 + i;
        const float4* bp4 = (const float4*)(wbuf + (i & 1) * 896 + t * 28);
        float pm = prot_mask[b * R_ + r];
        float mexr = __expf(-(1.0f - pm) * 1e9f);
        float rowS = 0.0f, rowE = 0.0f;
        float E0, E1, E2, E3;

        {
            float4 v0 = bp4[0], v1 = bp4[1], v2 = bp4[2], v3 = bp4[3];
            ELEM(v0.x, v0.y, v0.z, v0.w, v1.x, v1.y, v1.z, pm * fg4.x, mexf0, E0, zc0, lc0);
            ELEM(v1.w, v2.x, v2.y, v2.z, v2.w, v3.x, v3.y, pm * fg4.y, mexf1, E1, zc1, lc1);
            float4 v4 = bp4[4], v5 = bp4[5], v6 = bp4[6];
            ELEM(v3.z, v3.w, v4.x, v4.y, v4.z, v4.w, v5.x, pm * fg4.z, mexf2, E2, zc2, lc2);
            ELEM(v5.y, v5.z, v5.w, v6.x, v6.y, v6.z, v6.w, pm * fg4.w, mexf3, E3, zc3, lc3);
        }

        {   // packed fp16 store: one STG.64
            __half2 ha = __halves2half2(__float2half_rn(E0), __float2half_rn(E1));
            __half2 hb = __halves2half2(__float2half_rn(E2), __float2half_rn(E3));
            uint2 pk;
            pk.x = *reinterpret_cast<unsigned int*>(&ha);
            pk.y = *reinterpret_cast<unsigned int*>(&hb);
            ((uint2*)(E_h + (size_t)(b * R_ + r) * F_))[t] = pk;
        }

        rowS = warpAllSum(rowS);
        rowE = warpAllSum(rowE);
        float ps = rowS * pm;
        if (t == 0) { pscore_g[b * R_ + r] = ps; Zrow_g[b * R_ + r] = rowE; }
        float coef = __fdividef(ps, rowE);
        ab0 = fmaf(coef, E0, ab0);
        ab1 = fmaf(coef, E1, ab1);
        ab2 = fmaf(coef, E2, ab2);
        ab3 = fmaf(coef, E3, ab3);
        __syncwarp();
    }

    // epilogue: block-wide reduction into deterministic partial slots
    #pragma unroll
    for (int k = 0; k < K_; k++) { float v = warpSum(tk[k]); if (t == 0) tks[w][k] = v; }
    __syncthreads();
    float4* bb4 = (float4*)dbuf;
    bb4[w * 32 + t]       = make_float4(zc0, zc1, zc2, zc3);
    bb4[256 + w * 32 + t] = make_float4(lc0, lc1, lc2, lc3);
    bb4[512 + w * 32 + t] = make_float4(ab0, ab1, ab2, ab3);
    __syncthreads();
    if (tid < 128) {
        float s = 0.0f, s2 = 0.0f, s3 = 0.0f;
        #pragma unroll
        for (int ww = 0; ww < 8; ww++) {
            s  += dbuf[ww * 128 + tid];
            s2 += dbuf[1024 + ww * 128 + tid];
            s3 += dbuf[2048 + ww * 128 + tid];
        }
        Zcolp_g[(size_t)(b * NB1_ + blk) * F_ + tid]   = s;
        ligcolp_g[(size_t)(b * NB1_ + blk) * F_ + tid] = s2;
        abarp_g[(size_t)(b * NB1_ + blk) * F_ + tid]   = s3;
    } else if (tid < 128 + K_) {
        int k = tid - 128;
        float s = 0.0f;
        #pragma unroll
        for (int ww = 0; ww < 8; ww++) s += tks[ww][k];
        tstrp_g[(size_t)(b * NB1_ + blk) * 8 + k] = s * wshr[k];
    }
#if __CUDA_ARCH__ >= 900
    cudaTriggerProgrammaticLaunchCompletion();
#endif
}

// ====== K3: R13 prolog + main loop; elected last block finalizes ALL =======
__global__ void __launch_bounds__(256, 6) k3_epass(const float* __restrict__ protein_emb,
                        const float* __restrict__ ligand_emb,
                        const float* __restrict__ fg_mask,
                        const float* __restrict__ prot_mask,
                        const float* __restrict__ Wr, const float* __restrict__ Wf,
                        const float* __restrict__ W1, const float* __restrict__ W2) {
    int b = blockIdx.y, blk = blockIdx.x;
    int tid = threadIdx.x, w = tid >> 5, t = tid & 31;
    int f = tid & 127, q = tid >> 7;

    __shared__ __align__(16) float lco_sm[128];
    __shared__ float zsm[2][128], lsm[2][128];
    __shared__ __align__(16) float stage[2048];
    __shared__ unsigned int lastsh;

    // PDL prolog: L2 prefetch of head weights + ligand
    {
        int gb = b * NB3_ + blk;                       // 0..511
        long gid = (long)gb * 256 + tid;
        const long n1 = 4208, n2 = 4096, nr = 512, nl = 8192;
        if (gid < n1)                      l2pf((const char*)W1 + gid * 128);
        else if (gid < n1+n2)              l2pf((const char*)W2 + (gid-n1) * 128);
        else if (gid < n1+n2+nr)           l2pf((const char*)Wr + (gid-n1-n2) * 128);
        else if (gid < n1+n2+2*nr)         l2pf((const char*)Wf + (gid-n1-n2-nr) * 128);
        else if (gid < n1+n2+2*nr+nl)      l2pf((const char*)ligand_emb + (gid-n1-n2-2*nr) * 128);
    }
#if __CUDA_ARCH__ >= 900
    cudaGridDependencySynchronize();
#endif

    // lcoef from k1 column partials (zsm/lsm kept for the elected finalize)
    float zs = 0.0f, ls = 0.0f;
    for (int s = q * 16; s < q * 16 + 16; s++) {
        zs += Zcolp_g[(size_t)(b * NB1_ + s) * F_ + f];
        ls += ligcolp_g[(size_t)(b * NB1_ + s) * F_ + f];
    }
    zsm[q][f] = zs; lsm[q][f] = ls;
    __syncthreads();
    if (tid < 128) {
        float Zc  = zsm[0][tid] + zsm[1][tid];
        float lgc = lsm[0][tid] + lsm[1][tid];
        lco_sm[tid] = __fdividef(lgc * fg_mask[b * F_ + tid], Zc);
    }
    __syncthreads();
    float4 lco4 = ((const float4*)lco_sm)[t];

    // row loop: 8 warps x 4 rows, lane t owns f=4t..4t+3
    float4 Pa = make_float4(0.f, 0.f, 0.f, 0.f);
    float4 Ca = make_float4(0.f, 0.f, 0.f, 0.f);
    int rbase = blk * 32 + w * 4;
    #pragma unroll
    for (int i = 0; i < 4; i++) {
        int r = rbase + i;
        float ps = pscore_g[b * R_ + r];
        float pm = prot_mask[b * R_ + r];
        float mexr = __expf(-(1.0f - pm) * 1e9f);
        uint2 e2v = ((const uint2*)(E_h + (size_t)(b * R_ + r) * F_))[t];
        __half2 ha = *reinterpret_cast<__half2*>(&e2v.x);
        __half2 hb = *reinterpret_cast<__half2*>(&e2v.y);
        float2 fa = __half22float2(ha);
        float2 fb = __half22float2(hb);
        float dv = lco4.x * fa.x + lco4.y * fa.y + lco4.z * fb.x + lco4.w * fb.y;
        float craw = mexr * warpAllSum(dv);
        float4 P4 = ((const float4*)(protein_emb + (size_t)(b * R_ + r) * D_))[t];
        Pa.x = fmaf(ps, P4.x, Pa.x); Pa.y = fmaf(ps, P4.y, Pa.y);
        Pa.z = fmaf(ps, P4.z, Pa.z); Pa.w = fmaf(ps, P4.w, Pa.w);
        Ca.x = fmaf(craw, P4.x, Ca.x); Ca.y = fmaf(craw, P4.y, Ca.y);
        Ca.z = fmaf(craw, P4.z, Ca.z); Ca.w = fmaf(craw, P4.w, Ca.w);
    }

    __syncthreads();
    float4* st4 = (float4*)stage;
    st4[w * 32 + t]       = Pa;
    st4[256 + w * 32 + t] = Ca;
    __syncthreads();
    if (tid < 128) {
        float s = 0.0f;
        #pragma unroll
        for (int ww = 0; ww < 8; ww++) s += stage[ww * 128 + tid];
        Pwp_g[(size_t)(b * NB3_ + blk) * D_ + tid] = s;
    } else {
        float s = 0.0f;
        #pragma unroll
        for (int ww = 0; ww < 8; ww++) s += stage[1024 + ww * 128 + f];
        Cwp_g[(size_t)(b * NB3_ + blk) * D_ + f] = s;
    }

    // ---- per-batch finalize: last block computes everything khead needs ----
    __threadfence();
    __syncthreads();
    if (tid == 0) lastsh = atomicInc(&cnt3_g[b], NB3_ - 1);
    __syncthreads();
    if (lastsh != NB3_ - 1) {
#if __CUDA_ARCH__ >= 900
        cudaTriggerProgrammaticLaunchCompletion();
#endif
        return;
    }
    __threadfence();
    {
        // psum over pscore (4 elements/thread)
        float vv = pscore_g[b*R_+tid] + pscore_g[b*R_+256+tid]
                 + pscore_g[b*R_+512+tid] + pscore_g[b*R_+768+tid];
        float psum = blockReduceSum(vv, stage);
        float ip = __fdividef(1.0f, psum + 1e-8f);

        // lsum + lw from lsm (persisted from prolog)
        float fgv = 0.0f, lw0 = 0.0f;
        if (tid < 128) {
            float lgc = lsm[0][tid] + lsm[1][tid];
            fgv = fg_mask[b * F_ + tid];
            lw0 = lgc * fgv;
        }
        float lsum = blockReduceSum(lw0, stage);
        float il = __fdividef(1.0f, lsum + 1e-8f);

        // abar slot sums
        float as2 = 0.0f;
        for (int s = q * 16; s < q * 16 + 16; s++)
            as2 += abarp_g[(size_t)(b * NB1_ + s) * F_ + f];
        stage[q * 128 + f] = as2;
        // Pw/Cw slot sums
        float aP = 0.0f, aC = 0.0f;
        for (int s = q * 16; s < q * 16 + 16; s++) {
            aP += Pwp_g[(size_t)(b * NB3_ + s) * D_ + f];
            aC += Cwp_g[(size_t)(b * NB3_ + s) * D_ + f];
        }
        stage[256 + q * 128 + f] = aP;
        stage[512 + q * 128 + f] = aC;
        __syncthreads();
        if (tid < 128) {
            float absum = stage[tid] + stage[128 + tid];
            float mexf = __expf(-(1.0f - fgv) * 1e9f);
            lw_g[b * F_ + tid] = lw0 * il;
            la_g[b * F_ + tid] = absum * mexf * ip;
            Pws_g[b * D_ + tid] = (stage[256 + tid] + stage[384 + tid]) * ip;
            Cws_g[b * D_ + tid] = (stage[512 + tid] + stage[640 + tid]) * il;
        }
        if (tid == 0) {
            scal_g[b*4+0] = ip; scal_g[b*4+1] = il;
            scal_g[b*4+2] = psum * ip; scal_g[b*4+3] = lsum * il;
        }
        if (tid < K_) {
            float s = 0.0f;
            #pragma unroll
            for (int s2 = 0; s2 < NB1_; s2++) s += tstrp_g[(size_t)(b * NB1_ + s2) * 8 + tid];
            tst_g[b * 8 + tid] = s;
        }
    }
#if __CUDA_ARCH__ >= 900
    cudaTriggerProgrammaticLaunchCompletion();
#endif
}

// ====== KHEAD: pure tail — pooling + feat + norm + MLP =====================
__global__ void __launch_bounds__(1024, 1) khead(const float* __restrict__ ligand_emb,
                        const float* __restrict__ fg_mask,
                        const float* __restrict__ Wr, const float* __restrict__ br,
                        const float* __restrict__ Wf, const float* __restrict__ bf,
                        const float* __restrict__ W1, const float* __restrict__ b1,
                        const float* __restrict__ W2, const float* __restrict__ b2,
                        const float* __restrict__ W3, const float* __restrict__ b3,
                        float* __restrict__ dout, int osz) {
    int b = blockIdx.x, tid = threadIdx.x, w = tid >> 5, t = tid & 31;
    int f = tid & 127, q = tid >> 7;

    __shared__ float red[32];
    __shared__ float big[2048];
    __shared__ float lw_sm[128], la_s[128];
    __shared__ float Pws[128], Cws[128];
    __shared__ float gs[128], Ls[128];
    __shared__ float feat[FEAT_ + 1];
    __shared__ float h1[H_], h2[H2_];
    __shared__ float tst[8];

    // PDL prolog
    if (b == 0) for (int i = B_ + B_ * FEAT_ + tid; i < osz; i += 1024) dout[i] = 0.0f;
#if __CUDA_ARCH__ >= 900
    cudaGridDependencySynchronize();
#endif

    float spw = scal_g[b*4+2], slw = scal_g[b*4+3];
    if (tid < 128) {
        la_s[tid]  = la_g[b * F_ + tid];
        lw_sm[tid] = lw_g[b * F_ + tid];
        Pws[tid]   = Pws_g[b * D_ + tid];
        Cws[tid]   = Cws_g[b * D_ + tid];
    }
    if (tid < K_) tst[tid] = tst_g[b * 8 + tid];
    __syncthreads();

    // ligand pooling: 8 f-chunks x 128 d
    {
        float ag = 0.0f, aL = 0.0f;
        #pragma unroll
        for (int i = 0; i < 16; i++) {
            int ff = q * 16 + i;
            float lv = ligand_emb[(size_t)(b * F_ + ff) * D_ + f];
            ag += la_s[ff] * lv;
            aL += lw_sm[ff] * lv;
        }
        big[q * 128 + f] = ag;
        big[1024 + q * 128 + f] = aL;
    }
    __syncthreads();
    if (tid < 128) {
        float g = 0.0f, L = 0.0f;
        #pragma unroll
        for (int j = 0; j < 8; j++) { g += big[j * 128 + tid]; L += big[1024 + j * 128 + tid]; }
        gs[tid] = g; Ls[tid] = L;
    }
    __syncthreads();

    // feat rows: warps 0-15 -> Wr/gs, 16-31 -> Wf/Cws
    {
        const float* Wm = (w < 16) ? Wr : Wf;
        const float* vec = (w < 16) ? gs : Cws;
        int rb = (w & 15) * 8;
        #pragma unroll 1
        for (int i = 0; i < 2; i++) {
            int r0 = rb + i * 4;
            float p0=0.f,p1=0.f,p2=0.f,p3=0.f;
            #pragma unroll
            for (int u = 0; u < 4; u++) {
                int j = t + 32 * u;
                float g = vec[j];
                p0 += Wm[(r0+0)*D_ + j] * g;
                p1 += Wm[(r0+1)*D_ + j] * g;
                p2 += Wm[(r0+2)*D_ + j] * g;
                p3 += Wm[(r0+3)*D_ + j] * g;
            }
            p0 = warpSum(p0); p1 = warpSum(p1); p2 = warpSum(p2); p3 = warpSum(p3);
            if (t == 0) {
                if (w < 16) {
                    feat[r0+0] = Pws[r0+0] + p0 + spw * br[r0+0];
                    feat[r0+1] = Pws[r0+1] + p1 + spw * br[r0+1];
                    feat[r0+2] = Pws[r0+2] + p2 + spw * br[r0+2];
                    feat[r0+3] = Pws[r0+3] + p3 + spw * br[r0+3];
                } else {
                    feat[128+r0+0] = Ls[r0+0] + p0 + slw * bf[r0+0];
                    feat[128+r0+1] = Ls[r0+1] + p1 + slw * bf[r0+1];
                    feat[128+r0+2] = Ls[r0+2] + p2 + slw * bf[r0+2];
                    feat[128+r0+3] = Ls[r0+3] + p3 + slw * bf[r0+3];
                }
            }
        }
    }
    if (tid < K_) feat[2 * D_ + tid] = tst[tid];
    __syncthreads();

    // norm + normalized-feat output
    float sv = (tid < FEAT_) ? feat[tid] * feat[tid] : 0.0f;
    float nrm = blockReduceSum(sv, red);
    float inv = 1.0f / fmaxf(sqrtf(nrm), 1e-12f);
    if (tid < FEAT_) {
        int oi = B_ + b * FEAT_ + tid;
        if (oi < osz) dout[oi] = feat[tid] * inv;
    }

    // MLP layer 1: 512 rows, 16/warp, 4 per iteration
    {
        int rb = w * 16;
        #pragma unroll 1
        for (int i = 0; i < 4; i++) {
            int r0 = rb + i * 4;
            float p0=0.f,p1=0.f,p2=0.f,p3=0.f;
            #pragma unroll
            for (int u = 0; u < 8; u++) {
                int j = t + 32 * u;
                float fv = feat[j];
                p0 += W1[(r0+0)*FEAT_ + j] * fv;
                p1 += W1[(r0+1)*FEAT_ + j] * fv;
                p2 += W1[(r0+2)*FEAT_ + j] * fv;
                p3 += W1[(r0+3)*FEAT_ + j] * fv;
            }
            if (t < 7) {
                int j = 256 + t;
                float fv = feat[j];
                p0 += W1[(r0+0)*FEAT_ + j] * fv;
                p1 += W1[(r0+1)*FEAT_ + j] * fv;
                p2 += W1[(r0+2)*FEAT_ + j] * fv;
                p3 += W1[(r0+3)*FEAT_ + j] * fv;
            }
            p0 = warpSum(p0); p1 = warpSum(p1); p2 = warpSum(p2); p3 = warpSum(p3);
            if (t == 0) {
                h1[r0+0] = fmaxf(p0 + b1[r0+0], 0.0f);
                h1[r0+1] = fmaxf(p1 + b1[r0+1], 0.0f);
                h1[r0+2] = fmaxf(p2 + b1[r0+2], 0.0f);
                h1[r0+3] = fmaxf(p3 + b1[r0+3], 0.0f);
            }
        }
    }
    __syncthreads();

    // MLP layer 2: 256 rows, 8/warp, 2 per iteration
    {
        int rb = w * 8;
        #pragma unroll 1
        for (int i = 0; i < 4; i++) {
            int r0 = rb + i * 2;
            float p0=0.f,p1=0.f;
            #pragma unroll
            for (int u = 0; u < 16; u++) {
                int j = t + 32 * u;
                float hv = h1[j];
                p0 += W2[(r0+0)*H_ + j] * hv;
                p1 += W2[(r0+1)*H_ + j] * hv;
            }
            p0 = warpSum(p0); p1 = warpSum(p1);
            if (t == 0) {
                h2[r0+0] = fmaxf(p0 + b2[r0+0], 0.0f);
                h2[r0+1] = fmaxf(p1 + b2[r0+1], 0.0f);
            }
        }
    }
    __syncthreads();
    float pv = (tid < H2_) ? W3[tid] * h2[tid] : 0.0f;
    float pred = blockReduceSum(pv, red);
    if (tid == 0 && b < osz) dout[b] = pred + b3[0];
}

// ---------------- launch ----------------
extern "C" void kernel_launch(void* const* d_in, const int* in_sizes, int n_in,
                              void* d_out, int out_size) {
    const float* lig    = (const float*)d_in[0];
    const float* prot   = (const float*)d_in[1];
    const float* logits = (const float*)d_in[2];
    const float* fg     = (const float*)d_in[3];
    const float* pmsk   = (const float*)d_in[4];
    const float* tw     = (const float*)d_in[5];
    const float* Wr = (const float*)d_in[6];  const float* br = (const float*)d_in[7];
    const float* Wf = (const float*)d_in[8];  const float* bf = (const float*)d_in[9];
    const float* W1 = (const float*)d_in[10]; const float* b1 = (const float*)d_in[11];
    const float* W2 = (const float*)d_in[12]; const float* b2 = (const float*)d_in[13];
    const float* W3 = (const float*)d_in[14]; const float* b3 = (const float*)d_in[15];
    float* out = (float*)d_out;

    static int smem_set = 0;
    if (!smem_set) {
        cudaFuncSetAttribute(k1_logits, cudaFuncAttributeMaxDynamicSharedMemorySize, K1_SMEM);
        smem_set = 1;
    }

    k1_logits<<<dim3(NB1_, B_), 256, K1_SMEM>>>(logits, fg, pmsk, tw);

    {
        cudaLaunchConfig_t cfg = {};
        cfg.gridDim = dim3(NB3_, B_);
        cfg.blockDim = dim3(256, 1, 1);
        cfg.dynamicSmemBytes = 0;
        cfg.stream = 0;
        cudaLaunchAttribute attrs[1];
        attrs[0].id = cudaLaunchAttributeProgrammaticStreamSerialization;
        attrs[0].val.programmaticStreamSerializationAllowed = 1;
        cfg.attrs = attrs;
        cfg.numAttrs = 1;
        cudaLaunchKernelEx(&cfg, k3_epass, prot, lig, fg, pmsk, Wr, Wf, W1, W2);
    }

    {
        cudaLaunchConfig_t cfg = {};
        cfg.gridDim = dim3(B_, 1, 1);
        cfg.blockDim = dim3(1024, 1, 1);
        cfg.dynamicSmemBytes = 0;
        cfg.stream = 0;
        cudaLaunchAttribute attrs[1];
        attrs[0].id = cudaLaunchAttributeProgrammaticStreamSerialization;
        attrs[0].val.programmaticStreamSerializationAllowed = 1;
        cfg.attrs = attrs;
        cfg.numAttrs = 1;
        cudaLaunchKernelEx(&cfg, khead, lig, fg, Wr, br, Wf, bf,
                           W1, b1, W2, b2, W3, b3, out, out_size);
    }
}

// round 16
// speedup vs baseline: 1.1945x; 1.1072x over previous
#include <cuda_runtime.h>
#include <cuda_fp16.h>
#include <cstdint>
#include <math.h>

#define B_ 16
#define R_ 1024
#define F_ 128
#define D_ 128
#define K_ 7
#define H_ 512
#define H2_ 256
#define FEAT_ 263   // 2*D + K
#define NB1_ 32     // k1 blocks per batch (32 rows each)
#define NB3_ 32     // k3 blocks per batch (32 rows each)
#define K1_SMEM (8 * 2 * 896 * 4)   // 57344 B: per-warp double row buffers

// ---------------- device scratch (static, allocation-free) ----------------
__device__ __half E_h[B_ * R_ * F_];         // exp(masked S), fp16
__device__ float pscore_g[B_ * R_];
// global accumulators (REDG targets; zeroed by khead at end of each run)
__device__ float Zcolacc_g[B_ * F_];
__device__ float ligcolacc_g[B_ * F_];
__device__ float abaracc_g[B_ * F_];
__device__ float tstacc_g[B_ * 8];
__device__ float Pwacc_g[B_ * D_];
__device__ float Cwacc_g[B_ * D_];

// ---------------- helpers ----------------
__device__ __forceinline__ float warpSum(float v) {
    #pragma unroll
    for (int o = 16; o > 0; o >>= 1) v += __shfl_down_sync(0xffffffffu, v, o);
    return v;
}
__device__ __forceinline__ float warpAllSum(float v) {
    #pragma unroll
    for (int o = 16; o > 0; o >>= 1) v += __shfl_xor_sync(0xffffffffu, v, o);
    return v;
}
__device__ __forceinline__ float blockReduceSum(float v, float* sm) {
    int lane = threadIdx.x & 31, w = threadIdx.x >> 5;
    int nw = (blockDim.x + 31) >> 5;
    v = warpSum(v);
    if (lane == 0) sm[w] = v;
    __syncthreads();
    float r = (threadIdx.x < nw) ? sm[threadIdx.x] : 0.0f;
    if (w == 0) r = warpSum(r);
    if (threadIdx.x == 0) sm[0] = r;
    __syncthreads();
    r = sm[0];
    __syncthreads();
    return r;
}
__device__ __forceinline__ void l2pf(const void* p) {
    asm volatile("prefetch.global.L2 [%0];" :: "l"(p));
}
__device__ __forceinline__ void cpasync16(unsigned int saddr, const void* gptr) {
    asm volatile("cp.async.cg.shared.global [%0], [%1], 16;" :: "r"(saddr), "l"(gptr));
}
__device__ __forceinline__ void cpasync_commit() {
    asm volatile("cp.async.commit_group;" ::: "memory");
}
template<int N>
__device__ __forceinline__ void cpasync_wait() {
    asm volatile("cp.async.wait_group %0;" :: "n"(N) : "memory");
}

// per-element softmax+weights macro
#define ELEM(X0,X1,X2,X3,X4,X5,X6, PMF, MEXF, EOUT, ZC, LC) do {              \
    float e0_=__expf(X0), e1_=__expf(X1), e2_=__expf(X2), e3_=__expf(X3);      \
    float e4_=__expf(X4), e5_=__expf(X5), e6_=__expf(X6);                      \
    float s_ = ((e0_+e1_)+(e2_+e3_))+((e4_+e5_)+e6_);                          \
    float inv_ = __fdividef(1.0f, s_);                                         \
    float h_ = e0_*wshr[0]; h_=fmaf(e1_,wshr[1],h_); h_=fmaf(e2_,wshr[2],h_);  \
    h_=fmaf(e3_,wshr[3],h_); h_=fmaf(e4_,wshr[4],h_);                          \
    h_=fmaf(e5_,wshr[5],h_); h_=fmaf(e6_,wshr[6],h_);                          \
    tk[0]=fmaf(e0_,inv_,tk[0]); tk[1]=fmaf(e1_,inv_,tk[1]);                    \
    tk[2]=fmaf(e2_,inv_,tk[2]); tk[3]=fmaf(e3_,inv_,tk[3]);                    \
    tk[4]=fmaf(e4_,inv_,tk[4]); tk[5]=fmaf(e5_,inv_,tk[5]);                    \
    tk[6]=fmaf(e6_,inv_,tk[6]);                                                \
    float Sm_ = h_*inv_*(PMF);                                                 \
    float E_ = __expf(Sm_);                                                    \
    EOUT = E_; rowS += Sm_; rowE = fmaf(E_, (MEXF), rowE);                     \
    ZC = fmaf(E_, mexr, ZC); LC += Sm_;                                        \
} while(0)

// ====== K1: R13 mainloop; epilogue writes via fire-and-forget REDG =========
__global__ void __launch_bounds__(256, 4) k1_logits(const float* __restrict__ logits,
                          const float* __restrict__ fg_mask,
                          const float* __restrict__ prot_mask,
                          const float* __restrict__ tw) {
    extern __shared__ __align__(16) float dbuf[];   // 8 warps x 2 x 896 floats
    int b = blockIdx.y, blk = blockIdx.x;
    int tid = threadIdx.x, w = tid >> 5, t = tid & 31;

    __shared__ float tks[8][8];
    __shared__ float wsh_s[8];

    if (tid < K_) {
        float x = tw[tid];
        wsh_s[tid] = fmaxf(x, 0.0f) + log1pf(expf(-fabsf(x)));
    }
    __syncthreads();
    float wshr[K_];
    #pragma unroll
    for (int k = 0; k < K_; k++) wshr[k] = wsh_s[k];

    float4 fg4 = ((const float4*)(fg_mask + b * F_))[t];
    float mexf0 = __expf(-(1.0f - fg4.x) * 1e9f);
    float mexf1 = __expf(-(1.0f - fg4.y) * 1e9f);
    float mexf2 = __expf(-(1.0f - fg4.z) * 1e9f);
    float mexf3 = __expf(-(1.0f - fg4.w) * 1e9f);

    float zc0=0.f,zc1=0.f,zc2=0.f,zc3=0.f;
    float lc0=0.f,lc1=0.f,lc2=0.f,lc3=0.f;
    float ab0=0.f,ab1=0.f,ab2=0.f,ab3=0.f;
    float tk[K_];
    #pragma unroll
    for (int k = 0; k < K_; k++) tk[k] = 0.0f;

    int r0 = blk * 32 + w * 4;
    float* wbuf = dbuf + w * 1792;
    unsigned int sb = (unsigned int)__cvta_generic_to_shared(wbuf);

    const float* lbase = logits + (size_t)(b * R_) * 896;
    {   // prologue: row 0 -> buffer 0
        const float4* src = (const float4*)(lbase + (size_t)r0 * 896);
        #pragma unroll
        for (int j = 0; j < 7; j++) cpasync16(sb + (t + 32 * j) * 16, src + t + 32 * j);
        cpasync_commit();
    }

    for (int i = 0; i < 4; i++) {
        if (i < 3) {
            const float4* src = (const float4*)(lbase + (size_t)(r0 + i + 1) * 896);
            unsigned int sa = sb + ((i + 1) & 1) * 3584;
            #pragma unroll
            for (int j = 0; j < 7; j++) cpasync16(sa + (t + 32 * j) * 16, src + t + 32 * j);
            cpasync_commit();
            cpasync_wait<1>();
        } else {
            cpasync_wait<0>();
        }
        __syncwarp();

        int r = r0 + i;
        const float4* bp4 = (const float4*)(wbuf + (i & 1) * 896 + t * 28);
        float pm = prot_mask[b * R_ + r];
        float mexr = __expf(-(1.0f - pm) * 1e9f);
        float rowS = 0.0f, rowE = 0.0f;
        float E0, E1, E2, E3;

        {
            float4 v0 = bp4[0], v1 = bp4[1], v2 = bp4[2], v3 = bp4[3];
            ELEM(v0.x, v0.y, v0.z, v0.w, v1.x, v1.y, v1.z, pm * fg4.x, mexf0, E0, zc0, lc0);
            ELEM(v1.w, v2.x, v2.y, v2.z, v2.w, v3.x, v3.y, pm * fg4.y, mexf1, E1, zc1, lc1);
            float4 v4 = bp4[4], v5 = bp4[5], v6 = bp4[6];
            ELEM(v3.z, v3.w, v4.x, v4.y, v4.z, v4.w, v5.x, pm * fg4.z, mexf2, E2, zc2, lc2);
            ELEM(v5.y, v5.z, v5.w, v6.x, v6.y, v6.z, v6.w, pm * fg4.w, mexf3, E3, zc3, lc3);
        }

        {   // packed fp16 store: one STG.64
            __half2 ha = __halves2half2(__float2half_rn(E0), __float2half_rn(E1));
            __half2 hb = __halves2half2(__float2half_rn(E2), __float2half_rn(E3));
            uint2 pk;
            pk.x = *reinterpret_cast<unsigned int*>(&ha);
            pk.y = *reinterpret_cast<unsigned int*>(&hb);
            ((uint2*)(E_h + (size_t)(b * R_ + r) * F_))[t] = pk;
        }

        rowS = warpAllSum(rowS);
        rowE = warpAllSum(rowE);
        float ps = rowS * pm;
        if (t == 0) pscore_g[b * R_ + r] = ps;
        float coef = __fdividef(ps, rowE);
        ab0 = fmaf(coef, E0, ab0);
        ab1 = fmaf(coef, E1, ab1);
        ab2 = fmaf(coef, E2, ab2);
        ab3 = fmaf(coef, E3, ab3);
        __syncwarp();
    }

    // epilogue: block-wide reduction, then REDG into global accumulators
    #pragma unroll
    for (int k = 0; k < K_; k++) { float v = warpSum(tk[k]); if (t == 0) tks[w][k] = v; }
    __syncthreads();
    float4* bb4 = (float4*)dbuf;
    bb4[w * 32 + t]       = make_float4(zc0, zc1, zc2, zc3);
    bb4[256 + w * 32 + t] = make_float4(lc0, lc1, lc2, lc3);
    bb4[512 + w * 32 + t] = make_float4(ab0, ab1, ab2, ab3);
    __syncthreads();
    if (tid < 128) {
        float s = 0.0f, s2 = 0.0f, s3 = 0.0f;
        #pragma unroll
        for (int ww = 0; ww < 8; ww++) {
            s  += dbuf[ww * 128 + tid];
            s2 += dbuf[1024 + ww * 128 + tid];
            s3 += dbuf[2048 + ww * 128 + tid];
        }
        atomicAdd(&Zcolacc_g[b * F_ + tid], s);
        atomicAdd(&ligcolacc_g[b * F_ + tid], s2);
        atomicAdd(&abaracc_g[b * F_ + tid], s3);
    } else if (tid < 128 + K_) {
        int k = tid - 128;
        float s = 0.0f;
        #pragma unroll
        for (int ww = 0; ww < 8; ww++) s += tks[ww][k];
        atomicAdd(&tstacc_g[b * 8 + k], s * wshr[k]);
    }
#if __CUDA_ARCH__ >= 900
    cudaTriggerProgrammaticLaunchCompletion();
#endif
}

// ====== K3: 2-load lcoef prolog; Pw/Cw via REDG ============================
__global__ void __launch_bounds__(256, 6) k3_epass(const float* __restrict__ protein_emb,
                        const float* __restrict__ ligand_emb,
                        const float* __restrict__ fg_mask,
                        const float* __restrict__ prot_mask,
                        const float* __restrict__ Wr, const float* __restrict__ Wf,
                        const float* __restrict__ W1, const float* __restrict__ W2) {
    int b = blockIdx.y, blk = blockIdx.x;
    int tid = threadIdx.x, w = tid >> 5, t = tid & 31;
    int f = tid & 127;

    __shared__ __align__(16) float lco_sm[128];
    __shared__ __align__(16) float stage[2048];

    // PDL prolog: L2 prefetch of head weights + ligand (independent of k1)
    {
        int gb = b * NB3_ + blk;                       // 0..511
        long gid = (long)gb * 256 + tid;
        const long n1 = 4208, n2 = 4096, nr = 512, nl = 8192;
        if (gid < n1)                      l2pf((const char*)W1 + gid * 128);
        else if (gid < n1+n2)              l2pf((const char*)W2 + (gid-n1) * 128);
        else if (gid < n1+n2+nr)           l2pf((const char*)Wr + (gid-n1-n2) * 128);
        else if (gid < n1+n2+2*nr)         l2pf((const char*)Wf + (gid-n1-n2-nr) * 128);
        else if (gid < n1+n2+2*nr+nl)      l2pf((const char*)ligand_emb + (gid-n1-n2-2*nr) * 128);
    }
#if __CUDA_ARCH__ >= 900
    cudaGridDependencySynchronize();
#endif

    // lcoef directly from global accumulators (finalized by k1)
    if (tid < 128) {
        float Zc  = Zcolacc_g[b * F_ + tid];
        float lgc = ligcolacc_g[b * F_ + tid];
        lco_sm[tid] = __fdividef(lgc * fg_mask[b * F_ + tid], Zc);
    }
    __syncthreads();
    float4 lco4 = ((const float4*)lco_sm)[t];

    // row loop: 8 warps x 4 rows, lane t owns f=4t..4t+3
    float4 Pa = make_float4(0.f, 0.f, 0.f, 0.f);
    float4 Ca = make_float4(0.f, 0.f, 0.f, 0.f);
    int rbase = blk * 32 + w * 4;
    #pragma unroll
    for (int i = 0; i < 4; i++) {
        int r = rbase + i;
        float ps = pscore_g[b * R_ + r];
        float pm = prot_mask[b * R_ + r];
        float mexr = __expf(-(1.0f - pm) * 1e9f);
        uint2 e2v = ((const uint2*)(E_h + (size_t)(b * R_ + r) * F_))[t];
        __half2 ha = *reinterpret_cast<__half2*>(&e2v.x);
        __half2 hb = *reinterpret_cast<__half2*>(&e2v.y);
        float2 fa = __half22float2(ha);
        float2 fb = __half22float2(hb);
        float dv = lco4.x * fa.x + lco4.y * fa.y + lco4.z * fb.x + lco4.w * fb.y;
        float craw = mexr * warpAllSum(dv);
        float4 P4 = ((const float4*)(protein_emb + (size_t)(b * R_ + r) * D_))[t];
        Pa.x = fmaf(ps, P4.x, Pa.x); Pa.y = fmaf(ps, P4.y, Pa.y);
        Pa.z = fmaf(ps, P4.z, Pa.z); Pa.w = fmaf(ps, P4.w, Pa.w);
        Ca.x = fmaf(craw, P4.x, Ca.x); Ca.y = fmaf(craw, P4.y, Ca.y);
        Ca.z = fmaf(craw, P4.z, Ca.z); Ca.w = fmaf(craw, P4.w, Ca.w);
    }

    __syncthreads();
    float4* st4 = (float4*)stage;
    st4[w * 32 + t]       = Pa;
    st4[256 + w * 32 + t] = Ca;
    __syncthreads();
    if (tid < 128) {
        float s = 0.0f;
        #pragma unroll
        for (int ww = 0; ww < 8; ww++) s += stage[ww * 128 + tid];
        atomicAdd(&Pwacc_g[b * D_ + tid], s);
    } else {
        float s = 0.0f;
        #pragma unroll
        for (int ww = 0; ww < 8; ww++) s += stage[1024 + ww * 128 + f];
        atomicAdd(&Cwacc_g[b * D_ + f], s);
    }
#if __CUDA_ARCH__ >= 900
    cudaTriggerProgrammaticLaunchCompletion();
#endif
}

// ====== KHEAD: direct loads + pooling + feat + norm + MLP; zeroes accs =====
__global__ void __launch_bounds__(1024, 1) khead(const float* __restrict__ ligand_emb,
                        const float* __restrict__ fg_mask,
                        const float* __restrict__ Wr, const float* __restrict__ br,
                        const float* __restrict__ Wf, const float* __restrict__ bf,
                        const float* __restrict__ W1, const float* __restrict__ b1,
                        const float* __restrict__ W2, const float* __restrict__ b2,
                        const float* __restrict__ W3, const float* __restrict__ b3,
                        float* __restrict__ dout, int osz) {
    int b = blockIdx.x, tid = threadIdx.x, w = tid >> 5, t = tid & 31;
    int f = tid & 127, q = tid >> 7;

    __shared__ float red[32];
    __shared__ float big[2048];
    __shared__ float lw_sm[128], la_s[128];
    __shared__ float Pws[128], Cws[128];
    __shared__ float gs[128], Ls[128];
    __shared__ float feat[FEAT_ + 1];
    __shared__ float h1[H_], h2[H2_];
    __shared__ float tst[8];

    // PDL prolog
    if (b == 0) for (int i = B_ + B_ * FEAT_ + tid; i < osz; i += 1024) dout[i] = 0.0f;
#if __CUDA_ARCH__ >= 900
    cudaGridDependencySynchronize();
#endif

    // psum
    float v = pscore_g[b * R_ + tid];
    float psum = blockReduceSum(v, red);
    float ip = __fdividef(1.0f, psum + 1e-8f);
    float spw = psum * ip;

    // lsum + finalized vectors from accumulators
    float lw0 = 0.0f;
    if (tid < 128) lw0 = ligcolacc_g[b * F_ + tid] * fg_mask[b * F_ + tid];
    float lsum = blockReduceSum(lw0, red);
    float il = __fdividef(1.0f, lsum + 1e-8f);
    float slw = lsum * il;
    if (tid < 128) {
        float fg = fg_mask[b * F_ + tid];
        float mexf = __expf(-(1.0f - fg) * 1e9f);
        lw_sm[tid] = lw0 * il;
        la_s[tid]  = abaracc_g[b * F_ + tid] * mexf * ip;
        Pws[tid]   = Pwacc_g[b * D_ + tid] * ip;
        Cws[tid]   = Cwacc_g[b * D_ + tid] * il;
    }
    if (tid < K_) tst[tid] = tstacc_g[b * 8 + tid];
    __syncthreads();

    // ligand pooling: 8 f-chunks x 128 d
    {
        float ag = 0.0f, aL = 0.0f;
        #pragma unroll
        for (int i = 0; i < 16; i++) {
            int ff = q * 16 + i;
            float lv = ligand_emb[(size_t)(b * F_ + ff) * D_ + f];
            ag += la_s[ff] * lv;
            aL += lw_sm[ff] * lv;
        }
        big[q * 128 + f] = ag;
        big[1024 + q * 128 + f] = aL;
    }
    __syncthreads();
    if (tid < 128) {
        float g = 0.0f, L = 0.0f;
        #pragma unroll
        for (int j = 0; j < 8; j++) { g += big[j * 128 + tid]; L += big[1024 + j * 128 + tid]; }
        gs[tid] = g; Ls[tid] = L;
    }
    __syncthreads();

    // feat rows: warps 0-15 -> Wr/gs, 16-31 -> Wf/Cws
    {
        const float* Wm = (w < 16) ? Wr : Wf;
        const float* vec = (w < 16) ? gs : Cws;
        int rb = (w & 15) * 8;
        #pragma unroll 1
        for (int i = 0; i < 2; i++) {
            int r0 = rb + i * 4;
            float p0=0.f,p1=0.f,p2=0.f,p3=0.f;
            #pragma unroll
            for (int u = 0; u < 4; u++) {
                int j = t + 32 * u;
                float g = vec[j];
                p0 += Wm[(r0+0)*D_ + j] * g;
                p1 += Wm[(r0+1)*D_ + j] * g;
                p2 += Wm[(r0+2)*D_ + j] * g;
                p3 += Wm[(r0+3)*D_ + j] * g;
            }
            p0 = warpSum(p0); p1 = warpSum(p1); p2 = warpSum(p2); p3 = warpSum(p3);
            if (t == 0) {
                if (w < 16) {
                    feat[r0+0] = Pws[r0+0] + p0 + spw * br[r0+0];
                    feat[r0+1] = Pws[r0+1] + p1 + spw * br[r0+1];
                    feat[r0+2] = Pws[r0+2] + p2 + spw * br[r0+2];
                    feat[r0+3] = Pws[r0+3] + p3 + spw * br[r0+3];
                } else {
                    feat[128+r0+0] = Ls[r0+0] + p0 + slw * bf[r0+0];
                    feat[128+r0+1] = Ls[r0+1] + p1 + slw * bf[r0+1];
                    feat[128+r0+2] = Ls[r0+2] + p2 + slw * bf[r0+2];
                    feat[128+r0+3] = Ls[r0+3] + p3 + slw * bf[r0+3];
                }
            }
        }
    }
    if (tid < K_) feat[2 * D_ + tid] = tst[tid];
    __syncthreads();

    // norm + normalized-feat output
    float sv = (tid < FEAT_) ? feat[tid] * feat[tid] : 0.0f;
    float nrm = blockReduceSum(sv, red);
    float inv = 1.0f / fmaxf(sqrtf(nrm), 1e-12f);
    if (tid < FEAT_) {
        int oi = B_ + b * FEAT_ + tid;
        if (oi < osz) dout[oi] = feat[tid] * inv;
    }

    // MLP layer 1: 512 rows, 16/warp, 4 per iteration
    {
        int rb = w * 16;
        #pragma unroll 1
        for (int i = 0; i < 4; i++) {
            int r0 = rb + i * 4;
            float p0=0.f,p1=0.f,p2=0.f,p3=0.f;
            #pragma unroll
            for (int u = 0; u < 8; u++) {
                int j = t + 32 * u;
                float fv = feat[j];
                p0 += W1[(r0+0)*FEAT_ + j] * fv;
                p1 += W1[(r0+1)*FEAT_ + j] * fv;
                p2 += W1[(r0+2)*FEAT_ + j] * fv;
                p3 += W1[(r0+3)*FEAT_ + j] * fv;
            }
            if (t < 7) {
                int j = 256 + t;
                float fv = feat[j];
                p0 += W1[(r0+0)*FEAT_ + j] * fv;
                p1 += W1[(r0+1)*FEAT_ + j] * fv;
                p2 += W1[(r0+2)*FEAT_ + j] * fv;
                p3 += W1[(r0+3)*FEAT_ + j] * fv;
            }
            p0 = warpSum(p0); p1 = warpSum(p1); p2 = warpSum(p2); p3 = warpSum(p3);
            if (t == 0) {
                h1[r0+0] = fmaxf(p0 + b1[r0+0], 0.0f);
                h1[r0+1] = fmaxf(p1 + b1[r0+1], 0.0f);
                h1[r0+2] = fmaxf(p2 + b1[r0+2], 0.0f);
                h1[r0+3] = fmaxf(p3 + b1[r0+3], 0.0f);
            }
        }
    }
    __syncthreads();

    // MLP layer 2: 256 rows, 8/warp, 2 per iteration
    {
        int rb = w * 8;
        #pragma unroll 1
        for (int i = 0; i < 4; i++) {
            int r0 = rb + i * 2;
            float p0=0.f,p1=0.f;
            #pragma unroll
            for (int u = 0; u < 16; u++) {
                int j = t + 32 * u;
                float hv = h1[j];
                p0 += W2[(r0+0)*H_ + j] * hv;
                p1 += W2[(r0+1)*H_ + j] * hv;
            }
            p0 = warpSum(p0); p1 = warpSum(p1);
            if (t == 0) {
                h2[r0+0] = fmaxf(p0 + b2[r0+0], 0.0f);
                h2[r0+1] = fmaxf(p1 + b2[r0+1], 0.0f);
            }
        }
    }
    __syncthreads();
    float pv = (tid < H2_) ? W3[tid] * h2[tid] : 0.0f;
    float pred = blockReduceSum(pv, red);
    if (tid == 0 && b < osz) dout[b] = pred + b3[0];

    // zero accumulators for the next graph replay (all reads above are done
    // by this same block; program order suffices)
    if (tid < 128) {
        Zcolacc_g[b * F_ + tid] = 0.0f;
        ligcolacc_g[b * F_ + tid] = 0.0f;
        abaracc_g[b * F_ + tid] = 0.0f;
        Pwacc_g[b * D_ + tid] = 0.0f;
        Cwacc_g[b * D_ + tid] = 0.0f;
    }
    if (tid >= 128 && tid < 136) tstacc_g[b * 8 + (tid - 128)] = 0.0f;
}

// ---------------- launch ----------------
extern "C" void kernel_launch(void* const* d_in, const int* in_sizes, int n_in,
                              void* d_out, int out_size) {
    const float* lig    = (const float*)d_in[0];
    const float* prot   = (const float*)d_in[1];
    const float* logits = (const float*)d_in[2];
    const float* fg     = (const float*)d_in[3];
    const float* pmsk   = (const float*)d_in[4];
    const float* tw     = (const float*)d_in[5];
    const float* Wr = (const float*)d_in[6];  const float* br = (const float*)d_in[7];
    const float* Wf = (const float*)d_in[8];  const float* bf = (const float*)d_in[9];
    const float* W1 = (const float*)d_in[10]; const float* b1 = (const float*)d_in[11];
    const float* W2 = (const float*)d_in[12]; const float* b2 = (const float*)d_in[13];
    const float* W3 = (const float*)d_in[14]; const float* b3 = (const float*)d_in[15];
    float* out = (float*)d_out;

    static int smem_set = 0;
    if (!smem_set) {
        cudaFuncSetAttribute(k1_logits, cudaFuncAttributeMaxDynamicSharedMemorySize, K1_SMEM);
        smem_set = 1;
    }

    k1_logits<<<dim3(NB1_, B_), 256, K1_SMEM>>>(logits, fg, pmsk, tw);

    {
        cudaLaunchConfig_t cfg = {};
        cfg.gridDim = dim3(NB3_, B_);
        cfg.blockDim = dim3(256, 1, 1);
        cfg.dynamicSmemBytes = 0;
        cfg.stream = 0;
        cudaLaunchAttribute attrs[1];
        attrs[0].id = cudaLaunchAttributeProgrammaticStreamSerialization;
        attrs[0].val.programmaticStreamSerializationAllowed = 1;
        cfg.attrs = attrs;
        cfg.numAttrs = 1;
        cudaLaunchKernelEx(&cfg, k3_epass, prot, lig, fg, pmsk, Wr, Wf, W1, W2);
    }

    {
        cudaLaunchConfig_t cfg = {};
        cfg.gridDim = dim3(B_, 1, 1);
        cfg.blockDim = dim3(1024, 1, 1);
        cfg.dynamicSmemBytes = 0;
        cfg.stream = 0;
        cudaLaunchAttribute attrs[1];
        attrs[0].id = cudaLaunchAttributeProgrammaticStreamSerialization;
        attrs[0].val.programmaticStreamSerializationAllowed = 1;
        cfg.attrs = attrs;
        cfg.numAttrs = 1;
        cudaLaunchKernelEx(&cfg, khead, lig, fg, Wr, br, Wf, bf,
                           W1, b1, W2, b2, W3, b3, out, out_size);
    }
}

// round 17
// speedup vs baseline: 1.1986x; 1.0035x over previous
#include <cuda_runtime.h>
#include <cuda_fp16.h>
#include <cstdint>
#include <math.h>

#define B_ 16
#define R_ 1024
#define F_ 128
#define D_ 128
#define K_ 7
#define H_ 512
#define H2_ 256
#define FEAT_ 263   // 2*D + K
#define NB1_ 32     // k1 blocks per batch (32 rows each)
#define NB3_ 32     // k3 blocks per batch (32 rows each)
#define K1_SMEM (8 * 2 * 896 * 4)   // 57344 B: per-warp double row buffers

// ---------------- device scratch (static, allocation-free) ----------------
__device__ __half E_h[B_ * R_ * F_];         // exp(masked S), fp16
__device__ float pscore_g[B_ * R_];
// global accumulators (REDG targets; zeroed by khead at end of each run)
__device__ float Zcolacc_g[B_ * F_];
__device__ float ligcolacc_g[B_ * F_];
__device__ float abaracc_g[B_ * F_];
__device__ float tstacc_g[B_ * 8];
__device__ float Pwacc_g[B_ * D_];
__device__ float Cwacc_g[B_ * D_];

// ---------------- helpers ----------------
__device__ __forceinline__ float warpSum(float v) {
    #pragma unroll
    for (int o = 16; o > 0; o >>= 1) v += __shfl_down_sync(0xffffffffu, v, o);
    return v;
}
__device__ __forceinline__ float warpAllSum(float v) {
    #pragma unroll
    for (int o = 16; o > 0; o >>= 1) v += __shfl_xor_sync(0xffffffffu, v, o);
    return v;
}
__device__ __forceinline__ float blockReduceSum(float v, float* sm) {
    int lane = threadIdx.x & 31, w = threadIdx.x >> 5;
    int nw = (blockDim.x + 31) >> 5;
    v = warpSum(v);
    if (lane == 0) sm[w] = v;
    __syncthreads();
    float r = (threadIdx.x < nw) ? sm[threadIdx.x] : 0.0f;
    if (w == 0) r = warpSum(r);
    if (threadIdx.x == 0) sm[0] = r;
    __syncthreads();
    r = sm[0];
    __syncthreads();
    return r;
}
__device__ __forceinline__ void l2pf(const void* p) {
    asm volatile("prefetch.global.L2 [%0];" :: "l"(p));
}
__device__ __forceinline__ void cpasync16(unsigned int saddr, const void* gptr) {
    asm volatile("cp.async.cg.shared.global [%0], [%1], 16;" :: "r"(saddr), "l"(gptr));
}
__device__ __forceinline__ void cpasync_commit() {
    asm volatile("cp.async.commit_group;" ::: "memory");
}
template<int N>
__device__ __forceinline__ void cpasync_wait() {
    asm volatile("cp.async.wait_group %0;" :: "n"(N) : "memory");
}

// per-element softmax+weights macro
#define ELEM(X0,X1,X2,X3,X4,X5,X6, PMF, MEXF, EOUT, ZC, LC) do {              \
    float e0_=__expf(X0), e1_=__expf(X1), e2_=__expf(X2), e3_=__expf(X3);      \
    float e4_=__expf(X4), e5_=__expf(X5), e6_=__expf(X6);                      \
    float s_ = ((e0_+e1_)+(e2_+e3_))+((e4_+e5_)+e6_);                          \
    float inv_ = __fdividef(1.0f, s_);                                         \
    float h_ = e0_*wshr[0]; h_=fmaf(e1_,wshr[1],h_); h_=fmaf(e2_,wshr[2],h_);  \
    h_=fmaf(e3_,wshr[3],h_); h_=fmaf(e4_,wshr[4],h_);                          \
    h_=fmaf(e5_,wshr[5],h_); h_=fmaf(e6_,wshr[6],h_);                          \
    tk[0]=fmaf(e0_,inv_,tk[0]); tk[1]=fmaf(e1_,inv_,tk[1]);                    \
    tk[2]=fmaf(e2_,inv_,tk[2]); tk[3]=fmaf(e3_,inv_,tk[3]);                    \
    tk[4]=fmaf(e4_,inv_,tk[4]); tk[5]=fmaf(e5_,inv_,tk[5]);                    \
    tk[6]=fmaf(e6_,inv_,tk[6]);                                                \
    float Sm_ = h_*inv_*(PMF);                                                 \
    float E_ = __expf(Sm_);                                                    \
    EOUT = E_; rowS += Sm_; rowE = fmaf(E_, (MEXF), rowE);                     \
    ZC = fmaf(E_, mexr, ZC); LC += Sm_;                                        \
} while(0)

// ====== K1: R16 winner, unchanged ==========================================
__global__ void __launch_bounds__(256, 4) k1_logits(const float* __restrict__ logits,
                          const float* __restrict__ fg_mask,
                          const float* __restrict__ prot_mask,
                          const float* __restrict__ tw) {
    extern __shared__ __align__(16) float dbuf[];   // 8 warps x 2 x 896 floats
    int b = blockIdx.y, blk = blockIdx.x;
    int tid = threadIdx.x, w = tid >> 5, t = tid & 31;

    __shared__ float tks[8][8];
    __shared__ float wsh_s[8];

    if (tid < K_) {
        float x = tw[tid];
        wsh_s[tid] = fmaxf(x, 0.0f) + log1pf(expf(-fabsf(x)));
    }
    __syncthreads();
    float wshr[K_];
    #pragma unroll
    for (int k = 0; k < K_; k++) wshr[k] = wsh_s[k];

    float4 fg4 = ((const float4*)(fg_mask + b * F_))[t];
    float mexf0 = __expf(-(1.0f - fg4.x) * 1e9f);
    float mexf1 = __expf(-(1.0f - fg4.y) * 1e9f);
    float mexf2 = __expf(-(1.0f - fg4.z) * 1e9f);
    float mexf3 = __expf(-(1.0f - fg4.w) * 1e9f);

    float zc0=0.f,zc1=0.f,zc2=0.f,zc3=0.f;
    float lc0=0.f,lc1=0.f,lc2=0.f,lc3=0.f;
    float ab0=0.f,ab1=0.f,ab2=0.f,ab3=0.f;
    float tk[K_];
    #pragma unroll
    for (int k = 0; k < K_; k++) tk[k] = 0.0f;

    int r0 = blk * 32 + w * 4;
    float* wbuf = dbuf + w * 1792;
    unsigned int sb = (unsigned int)__cvta_generic_to_shared(wbuf);

    const float* lbase = logits + (size_t)(b * R_) * 896;
    {   // prologue: row 0 -> buffer 0
        const float4* src = (const float4*)(lbase + (size_t)r0 * 896);
        #pragma unroll
        for (int j = 0; j < 7; j++) cpasync16(sb + (t + 32 * j) * 16, src + t + 32 * j);
        cpasync_commit();
    }

    for (int i = 0; i < 4; i++) {
        if (i < 3) {
            const float4* src = (const float4*)(lbase + (size_t)(r0 + i + 1) * 896);
            unsigned int sa = sb + ((i + 1) & 1) * 3584;
            #pragma unroll
            for (int j = 0; j < 7; j++) cpasync16(sa + (t + 32 * j) * 16, src + t + 32 * j);
            cpasync_commit();
            cpasync_wait<1>();
        } else {
            cpasync_wait<0>();
        }
        __syncwarp();

        int r = r0 + i;
        const float4* bp4 = (const float4*)(wbuf + (i & 1) * 896 + t * 28);
        float pm = prot_mask[b * R_ + r];
        float mexr = __expf(-(1.0f - pm) * 1e9f);
        float rowS = 0.0f, rowE = 0.0f;
        float E0, E1, E2, E3;

        {
            float4 v0 = bp4[0], v1 = bp4[1], v2 = bp4[2], v3 = bp4[3];
            ELEM(v0.x, v0.y, v0.z, v0.w, v1.x, v1.y, v1.z, pm * fg4.x, mexf0, E0, zc0, lc0);
            ELEM(v1.w, v2.x, v2.y, v2.z, v2.w, v3.x, v3.y, pm * fg4.y, mexf1, E1, zc1, lc1);
            float4 v4 = bp4[4], v5 = bp4[5], v6 = bp4[6];
            ELEM(v3.z, v3.w, v4.x, v4.y, v4.z, v4.w, v5.x, pm * fg4.z, mexf2, E2, zc2, lc2);
            ELEM(v5.y, v5.z, v5.w, v6.x, v6.y, v6.z, v6.w, pm * fg4.w, mexf3, E3, zc3, lc3);
        }

        {   // packed fp16 store: one STG.64
            __half2 ha = __halves2half2(__float2half_rn(E0), __float2half_rn(E1));
            __half2 hb = __halves2half2(__float2half_rn(E2), __float2half_rn(E3));
            uint2 pk;
            pk.x = *reinterpret_cast<unsigned int*>(&ha);
            pk.y = *reinterpret_cast<unsigned int*>(&hb);
            ((uint2*)(E_h + (size_t)(b * R_ + r) * F_))[t] = pk;
        }

        rowS = warpAllSum(rowS);
        rowE = warpAllSum(rowE);
        float ps = rowS * pm;
        if (t == 0) pscore_g[b * R_ + r] = ps;
        float coef = __fdividef(ps, rowE);
        ab0 = fmaf(coef, E0, ab0);
        ab1 = fmaf(coef, E1, ab1);
        ab2 = fmaf(coef, E2, ab2);
        ab3 = fmaf(coef, E3, ab3);
        __syncwarp();
    }

    // epilogue: block-wide reduction, then REDG into global accumulators
    #pragma unroll
    for (int k = 0; k < K_; k++) { float v = warpSum(tk[k]); if (t == 0) tks[w][k] = v; }
    __syncthreads();
    float4* bb4 = (float4*)dbuf;
    bb4[w * 32 + t]       = make_float4(zc0, zc1, zc2, zc3);
    bb4[256 + w * 32 + t] = make_float4(lc0, lc1, lc2, lc3);
    bb4[512 + w * 32 + t] = make_float4(ab0, ab1, ab2, ab3);
    __syncthreads();
    if (tid < 128) {
        float s = 0.0f, s2 = 0.0f, s3 = 0.0f;
        #pragma unroll
        for (int ww = 0; ww < 8; ww++) {
            s  += dbuf[ww * 128 + tid];
            s2 += dbuf[1024 + ww * 128 + tid];
            s3 += dbuf[2048 + ww * 128 + tid];
        }
        atomicAdd(&Zcolacc_g[b * F_ + tid], s);
        atomicAdd(&ligcolacc_g[b * F_ + tid], s2);
        atomicAdd(&abaracc_g[b * F_ + tid], s3);
    } else if (tid < 128 + K_) {
        int k = tid - 128;
        float s = 0.0f;
        #pragma unroll
        for (int ww = 0; ww < 8; ww++) s += tks[ww][k];
        atomicAdd(&tstacc_g[b * 8 + k], s * wshr[k]);
    }
#if __CUDA_ARCH__ >= 900
    cudaTriggerProgrammaticLaunchCompletion();
#endif
}

// ====== K3: phase-split row loop (overlapped shuffle chains) ===============
__global__ void __launch_bounds__(256, 6) k3_epass(const float* __restrict__ protein_emb,
                        const float* __restrict__ ligand_emb,
                        const float* __restrict__ fg_mask,
                        const float* __restrict__ prot_mask,
                        const float* __restrict__ Wr, const float* __restrict__ Wf,
                        const float* __restrict__ W1, const float* __restrict__ W2) {
    int b = blockIdx.y, blk = blockIdx.x;
    int tid = threadIdx.x, w = tid >> 5, t = tid & 31;
    int f = tid & 127;

    __shared__ __align__(16) float lco_sm[128];
    __shared__ __align__(16) float stage[2048];

    // PDL prolog: L2 prefetch of head weights + ligand (independent of k1)
    {
        int gb = b * NB3_ + blk;                       // 0..511
        long gid = (long)gb * 256 + tid;
        const long n1 = 4208, n2 = 4096, nr = 512, nl = 8192;
        if (gid < n1)                      l2pf((const char*)W1 + gid * 128);
        else if (gid < n1+n2)              l2pf((const char*)W2 + (gid-n1) * 128);
        else if (gid < n1+n2+nr)           l2pf((const char*)Wr + (gid-n1-n2) * 128);
        else if (gid < n1+n2+2*nr)         l2pf((const char*)Wf + (gid-n1-n2-nr) * 128);
        else if (gid < n1+n2+2*nr+nl)      l2pf((const char*)ligand_emb + (gid-n1-n2-2*nr) * 128);
    }
#if __CUDA_ARCH__ >= 900
    cudaGridDependencySynchronize();
#endif

    // lcoef directly from global accumulators (finalized by k1)
    if (tid < 128) {
        float Zc  = Zcolacc_g[b * F_ + tid];
        float lgc = ligcolacc_g[b * F_ + tid];
        lco_sm[tid] = __fdividef(lgc * fg_mask[b * F_ + tid], Zc);
    }
    __syncthreads();
    float4 lco4 = ((const float4*)lco_sm)[t];

    // row loop: 8 warps x 4 rows, PHASE-SPLIT for latency overlap
    int rbase = blk * 32 + w * 4;
    float ps[4], mexr[4], dv[4];
    float2 fa[4], fb[4];

    // phase 1: all loads + dot products (independent; loads pipeline)
    #pragma unroll
    for (int i = 0; i < 4; i++) {
        int r = rbase + i;
        ps[i] = pscore_g[b * R_ + r];
        float pm = prot_mask[b * R_ + r];
        mexr[i] = __expf(-(1.0f - pm) * 1e9f);
        uint2 e2v = ((const uint2*)(E_h + (size_t)(b * R_ + r) * F_))[t];
        __half2 ha = *reinterpret_cast<__half2*>(&e2v.x);
        __half2 hb = *reinterpret_cast<__half2*>(&e2v.y);
        fa[i] = __half22float2(ha);
        fb[i] = __half22float2(hb);
        dv[i] = lco4.x * fa[i].x + lco4.y * fa[i].y + lco4.z * fb[i].x + lco4.w * fb[i].y;
    }
    // phase 2: 4 independent warp reductions (chains interleave)
    #pragma unroll
    for (int i = 0; i < 4; i++) dv[i] = warpAllSum(dv[i]);

    // phase 3: P loads + accumulation
    float4 Pa = make_float4(0.f, 0.f, 0.f, 0.f);
    float4 Ca = make_float4(0.f, 0.f, 0.f, 0.f);
    #pragma unroll
    for (int i = 0; i < 4; i++) {
        int r = rbase + i;
        float craw = mexr[i] * dv[i];
        float4 P4 = ((const float4*)(protein_emb + (size_t)(b * R_ + r) * D_))[t];
        Pa.x = fmaf(ps[i], P4.x, Pa.x); Pa.y = fmaf(ps[i], P4.y, Pa.y);
        Pa.z = fmaf(ps[i], P4.z, Pa.z); Pa.w = fmaf(ps[i], P4.w, Pa.w);
        Ca.x = fmaf(craw, P4.x, Ca.x); Ca.y = fmaf(craw, P4.y, Ca.y);
        Ca.z = fmaf(craw, P4.z, Ca.z); Ca.w = fmaf(craw, P4.w, Ca.w);
    }

    __syncthreads();
    float4* st4 = (float4*)stage;
    st4[w * 32 + t]       = Pa;
    st4[256 + w * 32 + t] = Ca;
    __syncthreads();
    if (tid < 128) {
        float s = 0.0f;
        #pragma unroll
        for (int ww = 0; ww < 8; ww++) s += stage[ww * 128 + tid];
        atomicAdd(&Pwacc_g[b * D_ + tid], s);
    } else {
        float s = 0.0f;
        #pragma unroll
        for (int ww = 0; ww < 8; ww++) s += stage[1024 + ww * 128 + f];
        atomicAdd(&Cwacc_g[b * D_ + f], s);
    }
#if __CUDA_ARCH__ >= 900
    cudaTriggerProgrammaticLaunchCompletion();
#endif
}

// ====== KHEAD: direct loads + pooling + feat + norm + MLP; zeroes accs =====
__global__ void __launch_bounds__(1024, 1) khead(const float* __restrict__ ligand_emb,
                        const float* __restrict__ fg_mask,
                        const float* __restrict__ Wr, const float* __restrict__ br,
                        const float* __restrict__ Wf, const float* __restrict__ bf,
                        const float* __restrict__ W1, const float* __restrict__ b1,
                        const float* __restrict__ W2, const float* __restrict__ b2,
                        const float* __restrict__ W3, const float* __restrict__ b3,
                        float* __restrict__ dout, int osz) {
    int b = blockIdx.x, tid = threadIdx.x, w = tid >> 5, t = tid & 31;
    int f = tid & 127, q = tid >> 7;

    __shared__ float red[32];
    __shared__ float big[2048];
    __shared__ float lw_sm[128], la_s[128];
    __shared__ float Pws[128], Cws[128];
    __shared__ float gs[128], Ls[128];
    __shared__ float feat[FEAT_ + 1];
    __shared__ float h1[H_], h2[H2_];
    __shared__ float tst[8];

    // PDL prolog
    if (b == 0) for (int i = B_ + B_ * FEAT_ + tid; i < osz; i += 1024) dout[i] = 0.0f;
#if __CUDA_ARCH__ >= 900
    cudaGridDependencySynchronize();
#endif

    // psum
    float v = pscore_g[b * R_ + tid];
    float psum = blockReduceSum(v, red);
    float ip = __fdividef(1.0f, psum + 1e-8f);
    float spw = psum * ip;

    // lsum + finalized vectors from accumulators
    float lw0 = 0.0f;
    if (tid < 128) lw0 = ligcolacc_g[b * F_ + tid] * fg_mask[b * F_ + tid];
    float lsum = blockReduceSum(lw0, red);
    float il = __fdividef(1.0f, lsum + 1e-8f);
    float slw = lsum * il;
    if (tid < 128) {
        float fg = fg_mask[b * F_ + tid];
        float mexf = __expf(-(1.0f - fg) * 1e9f);
        lw_sm[tid] = lw0 * il;
        la_s[tid]  = abaracc_g[b * F_ + tid] * mexf * ip;
        Pws[tid]   = Pwacc_g[b * D_ + tid] * ip;
        Cws[tid]   = Cwacc_g[b * D_ + tid] * il;
    }
    if (tid < K_) tst[tid] = tstacc_g[b * 8 + tid];
    __syncthreads();

    // ligand pooling: 8 f-chunks x 128 d
    {
        float ag = 0.0f, aL = 0.0f;
        #pragma unroll
        for (int i = 0; i < 16; i++) {
            int ff = q * 16 + i;
            float lv = ligand_emb[(size_t)(b * F_ + ff) * D_ + f];
            ag += la_s[ff] * lv;
            aL += lw_sm[ff] * lv;
        }
        big[q * 128 + f] = ag;
        big[1024 + q * 128 + f] = aL;
    }
    __syncthreads();
    if (tid < 128) {
        float g = 0.0f, L = 0.0f;
        #pragma unroll
        for (int j = 0; j < 8; j++) { g += big[j * 128 + tid]; L += big[1024 + j * 128 + tid]; }
        gs[tid] = g; Ls[tid] = L;
    }
    __syncthreads();

    // feat rows: warps 0-15 -> Wr/gs, 16-31 -> Wf/Cws
    {
        const float* Wm = (w < 16) ? Wr : Wf;
        const float* vec = (w < 16) ? gs : Cws;
        int rb = (w & 15) * 8;
        #pragma unroll 1
        for (int i = 0; i < 2; i++) {
            int r0 = rb + i * 4;
            float p0=0.f,p1=0.f,p2=0.f,p3=0.f;
            #pragma unroll
            for (int u = 0; u < 4; u++) {
                int j = t + 32 * u;
                float g = vec[j];
                p0 += Wm[(r0+0)*D_ + j] * g;
                p1 += Wm[(r0+1)*D_ + j] * g;
                p2 += Wm[(r0+2)*D_ + j] * g;
                p3 += Wm[(r0+3)*D_ + j] * g;
            }
            p0 = warpSum(p0); p1 = warpSum(p1); p2 = warpSum(p2); p3 = warpSum(p3);
            if (t == 0) {
                if (w < 16) {
                    feat[r0+0] = Pws[r0+0] + p0 + spw * br[r0+0];
                    feat[r0+1] = Pws[r0+1] + p1 + spw * br[r0+1];
                    feat[r0+2] = Pws[r0+2] + p2 + spw * br[r0+2];
                    feat[r0+3] = Pws[r0+3] + p3 + spw * br[r0+3];
                } else {
                    feat[128+r0+0] = Ls[r0+0] + p0 + slw * bf[r0+0];
                    feat[128+r0+1] = Ls[r0+1] + p1 + slw * bf[r0+1];
                    feat[128+r0+2] = Ls[r0+2] + p2 + slw * bf[r0+2];
                    feat[128+r0+3] = Ls[r0+3] + p3 + slw * bf[r0+3];
                }
            }
        }
    }
    if (tid < K_) feat[2 * D_ + tid] = tst[tid];
    __syncthreads();

    // norm + normalized-feat output
    float sv = (tid < FEAT_) ? feat[tid] * feat[tid] : 0.0f;
    float nrm = blockReduceSum(sv, red);
    float inv = 1.0f / fmaxf(sqrtf(nrm), 1e-12f);
    if (tid < FEAT_) {
        int oi = B_ + b * FEAT_ + tid;
        if (oi < osz) dout[oi] = feat[tid] * inv;
    }

    // MLP layer 1: 512 rows, 16/warp, 4 per iteration
    {
        int rb = w * 16;
        #pragma unroll 1
        for (int i = 0; i < 4; i++) {
            int r0 = rb + i * 4;
            float p0=0.f,p1=0.f,p2=0.f,p3=0.f;
            #pragma unroll
            for (int u = 0; u < 8; u++) {
                int j = t + 32 * u;
                float fv = feat[j];
                p0 += W1[(r0+0)*FEAT_ + j] * fv;
                p1 += W1[(r0+1)*FEAT_ + j] * fv;
                p2 += W1[(r0+2)*FEAT_ + j] * fv;
                p3 += W1[(r0+3)*FEAT_ + j] * fv;
            }
            if (t < 7) {
                int j = 256 + t;
                float fv = feat[j];
                p0 += W1[(r0+0)*FEAT_ + j] * fv;
                p1 += W1[(r0+1)*FEAT_ + j] * fv;
                p2 += W1[(r0+2)*FEAT_ + j] * fv;
                p3 += W1[(r0+3)*FEAT_ + j] * fv;
            }
            p0 = warpSum(p0); p1 = warpSum(p1); p2 = warpSum(p2); p3 = warpSum(p3);
            if (t == 0) {
                h1[r0+0] = fmaxf(p0 + b1[r0+0], 0.0f);
                h1[r0+1] = fmaxf(p1 + b1[r0+1], 0.0f);
                h1[r0+2] = fmaxf(p2 + b1[r0+2], 0.0f);
                h1[r0+3] = fmaxf(p3 + b1[r0+3], 0.0f);
            }
        }
    }
    __syncthreads();

    // MLP layer 2: 256 rows, 8/warp, 2 per iteration
    {
        int rb = w * 8;
        #pragma unroll 1
        for (int i = 0; i < 4; i++) {
            int r0 = rb + i * 2;
            float p0=0.f,p1=0.f;
            #pragma unroll
            for (int u = 0; u < 16; u++) {
                int j = t + 32 * u;
                float hv = h1[j];
                p0 += W2[(r0+0)*H_ + j] * hv;
                p1 += W2[(r0+1)*H_ + j] * hv;
            }
            p0 = warpSum(p0); p1 = warpSum(p1);
            if (t == 0) {
                h2[r0+0] = fmaxf(p0 + b2[r0+0], 0.0f);
                h2[r0+1] = fmaxf(p1 + b2[r0+1], 0.0f);
            }
        }
    }
    __syncthreads();
    float pv = (tid < H2_) ? W3[tid] * h2[tid] : 0.0f;
    float pred = blockReduceSum(pv, red);
    if (tid == 0 && b < osz) dout[b] = pred + b3[0];

    // zero accumulators for the next graph replay
    if (tid < 128) {
        Zcolacc_g[b * F_ + tid] = 0.0f;
        ligcolacc_g[b * F_ + tid] = 0.0f;
        abaracc_g[b * F_ + tid] = 0.0f;
        Pwacc_g[b * D_ + tid] = 0.0f;
        Cwacc_g[b * D_ + tid] = 0.0f;
    }
    if (tid >= 128 && tid < 136) tstacc_g[b * 8 + (tid - 128)] = 0.0f;
}

// ---------------- launch ----------------
extern "C" void kernel_launch(void* const* d_in, const int* in_sizes, int n_in,
                              void* d_out, int out_size) {
    const float* lig    = (const float*)d_in[0];
    const float* prot   = (const float*)d_in[1];
    const float* logits = (const float*)d_in[2];
    const float* fg     = (const float*)d_in[3];
    const float* pmsk   = (const float*)d_in[4];
    const float* tw     = (const float*)d_in[5];
    const float* Wr = (const float*)d_in[6];  const float* br = (const float*)d_in[7];
    const float* Wf = (const float*)d_in[8];  const float* bf = (const float*)d_in[9];
    const float* W1 = (const float*)d_in[10]; const float* b1 = (const float*)d_in[11];
    const float* W2 = (const float*)d_in[12]; const float* b2 = (const float*)d_in[13];
    const float* W3 = (const float*)d_in[14]; const float* b3 = (const float*)d_in[15];
    float* out = (float*)d_out;

    static int smem_set = 0;
    if (!smem_set) {
        cudaFuncSetAttribute(k1_logits, cudaFuncAttributeMaxDynamicSharedMemorySize, K1_SMEM);
        smem_set = 1;
    }

    k1_logits<<<dim3(NB1_, B_), 256, K1_SMEM>>>(logits, fg, pmsk, tw);

    {
        cudaLaunchConfig_t cfg = {};
        cfg.gridDim = dim3(NB3_, B_);
        cfg.blockDim = dim3(256, 1, 1);
        cfg.dynamicSmemBytes = 0;
        cfg.stream = 0;
        cudaLaunchAttribute attrs[1];
        attrs[0].id = cudaLaunchAttributeProgrammaticStreamSerialization;
        attrs[0].val.programmaticStreamSerializationAllowed = 1;
        cfg.attrs = attrs;
        cfg.numAttrs = 1;
        cudaLaunchKernelEx(&cfg, k3_epass, prot, lig, fg, pmsk, Wr, Wf, W1, W2);
    }

    {
        cudaLaunchConfig_t cfg = {};
        cfg.gridDim = dim3(B_, 1, 1);
        cfg.blockDim = dim3(1024, 1, 1);
        cfg.dynamicSmemBytes = 0;
        cfg.stream = 0;
        cudaLaunchAttribute attrs[1];
        attrs[0].id = cudaLaunchAttributeProgrammaticStreamSerialization;
        attrs[0].val.programmaticStreamSerializationAllowed = 1;
        cfg.attrs = attrs;
        cfg.numAttrs = 1;
        cudaLaunchKernelEx(&cfg, khead, lig, fg, Wr, br, Wf, bf,
                           W1, b1, W2, b2, W3, b3, out, out_size);
    }
}